// round 3
// baseline (speedup 1.0000x reference)
#include <cuda_runtime.h>
#include <math.h>

#define EPSF 1e-7f
#define BATCH 256

// ---------------- scratch (device globals: no cudaMalloc allowed) ----------------
__device__ float g_x1[BATCH * 20 * 20 * 256];     // conv1 output (NHWC)  105 MB
__device__ float g_u[BATCH * 1152 * 8];           // primary caps          9.4 MB
__device__ float g_uhat[BATCH * 1152 * 160];      // u_hat [b][i][j*16+k] 189 MB
__device__ float g_bl[BATCH * 1152 * 10];         // routing logits
__device__ float g_h0[BATCH * 160];               // masked v
__device__ float g_h1[BATCH * 512];
__device__ float g_h2[BATCH * 1024];

// ---------------- packed f32x2 helpers (Blackwell FFMA2) ----------------
__device__ __forceinline__ unsigned long long pack2(float x) {
    unsigned long long r;
    asm("mov.b64 %0, {%1, %1};" : "=l"(r) : "f"(x));
    return r;
}
__device__ __forceinline__ unsigned long long fma2(unsigned long long a,
                                                   unsigned long long b,
                                                   unsigned long long c) {
    unsigned long long d;
    asm("fma.rn.f32x2 %0, %1, %2, %3;" : "=l"(d) : "l"(a), "l"(b), "l"(c));
    return d;
}
__device__ __forceinline__ float2 unpk2(unsigned long long v) {
    float2 r;
    asm("mov.b64 {%0, %1}, %2;" : "=f"(r.x), "=f"(r.y) : "l"(v));
    return r;
}

// =====================================================================
// Kernel 1: conv1 9x9 stride1 VALID, 1->256 ch, +bias, ReLU
// grid 512 = (image, half), 256 threads = output channel
// =====================================================================
__global__ __launch_bounds__(256) void conv1_kernel(
    const float* __restrict__ x, const float* __restrict__ w,
    const float* __restrict__ bias)
{
    __shared__ float img[784];
    const int b = blockIdx.x >> 1;
    const int half = blockIdx.x & 1;
    const int c = threadIdx.x;

    for (int t = threadIdx.x; t < 784; t += 256) img[t] = x[b * 784 + t];

    float wr[81];
#pragma unroll
    for (int k = 0; k < 81; k++) wr[k] = w[k * 256 + c];
    const float bv = bias[c];
    __syncthreads();

    const int oy0 = half * 10;
    for (int oy = oy0; oy < oy0 + 10; oy++) {
        for (int ox = 0; ox < 20; ox++) {
            float acc = bv;
            const float* ip = img + oy * 28 + ox;
#pragma unroll
            for (int ky = 0; ky < 9; ky++) {
#pragma unroll
                for (int kx = 0; kx < 9; kx++) {
                    acc += ip[ky * 28 + kx] * wr[ky * 9 + kx];
                }
            }
            g_x1[((b * 20 + oy) * 20 + ox) * 256 + c] = fmaxf(acc, 0.f);
        }
    }
}

// =====================================================================
// Kernel 2: primary-caps conv as implicit GEMM.
// out[m, n] = sum_k A[m,k] * W[k,n] + bias[n]
//   m = b*36 + oy*6 + ox   (9216),  n = oc (256),  k = ky*2304 + (kx*256+ic) (20736)
//   A[m, k] = g_x1[base(m) + ky*5120 + (kx*256+ic)]  -> contiguous per ky band
// BM=64 BN=128 BK=16, 256 threads, 4x8 microtile as f32x2 pairs.
// =====================================================================
__global__ __launch_bounds__(256) void pc_kernel(
    const float* __restrict__ w, const float* __restrict__ bias)
{
    __shared__ float As[2][16][68];
    __shared__ float Bs[2][16][128];

    const int tid = threadIdx.x;
    const int nbase = blockIdx.y * 128;

    // A-load mapping: each thread loads one float4 (64 rows x 4 f4/row)
    const int lrow = tid >> 2;
    const int kq = tid & 3;
    const int m = blockIdx.x * 64 + lrow;
    const int bimg = m / 36;
    const int p = m % 36;
    const float* aptr = g_x1 + bimg * 102400 + (p / 6) * 10240 + (p % 6) * 512 + kq * 4;

    // B-load mapping: two float4 per thread (16 rows x 32 f4/row)
    const int brow = tid >> 5;            // 0..7
    const int bc = (tid & 31) * 4;
    const float* wptr = w + nbase;

    const int ty = tid >> 4;              // 0..15 -> rows ty*4..ty*4+3
    const int tx = tid & 15;              // cols tx*4.. and 64+tx*4..

    unsigned long long acc[4][4];
#pragma unroll
    for (int r = 0; r < 4; r++)
#pragma unroll
        for (int q = 0; q < 4; q++) acc[r][q] = 0ull;

    // prologue: tile (ky=0, kseg=0)
    float4 aReg = *(const float4*)(aptr);
    float4 bReg0 = *(const float4*)(wptr + (size_t)brow * 256 + bc);
    float4 bReg1 = *(const float4*)(wptr + (size_t)(brow + 8) * 256 + bc);
    As[0][kq * 4 + 0][lrow] = aReg.x;
    As[0][kq * 4 + 1][lrow] = aReg.y;
    As[0][kq * 4 + 2][lrow] = aReg.z;
    As[0][kq * 4 + 3][lrow] = aReg.w;
    *(float4*)&Bs[0][brow][bc] = bReg0;
    *(float4*)&Bs[0][brow + 8][bc] = bReg1;
    __syncthreads();

    int buf = 0;
    for (int ky = 0; ky < 9; ky++) {
        for (int kseg = 0; kseg < 144; kseg++) {
            const bool last = (ky == 8) && (kseg == 143);
            if (!last) {
                int nky = ky, nseg = kseg + 1;
                if (nseg == 144) { nseg = 0; nky++; }
                const int aoff = nky * 5120 + nseg * 16;
                const int k0 = nky * 2304 + nseg * 16;
                aReg = *(const float4*)(aptr + aoff);
                bReg0 = *(const float4*)(wptr + (size_t)(k0 + brow) * 256 + bc);
                bReg1 = *(const float4*)(wptr + (size_t)(k0 + brow + 8) * 256 + bc);
            }
#pragma unroll
            for (int kk = 0; kk < 16; kk++) {
                const float4 a4 = *(const float4*)&As[buf][kk][ty * 4];
                const ulonglong2 b01 = *(const ulonglong2*)&Bs[buf][kk][tx * 4];
                const ulonglong2 b23 = *(const ulonglong2*)&Bs[buf][kk][64 + tx * 4];
                const unsigned long long a0 = pack2(a4.x);
                const unsigned long long a1 = pack2(a4.y);
                const unsigned long long a2 = pack2(a4.z);
                const unsigned long long a3 = pack2(a4.w);
                acc[0][0] = fma2(a0, b01.x, acc[0][0]);
                acc[0][1] = fma2(a0, b01.y, acc[0][1]);
                acc[0][2] = fma2(a0, b23.x, acc[0][2]);
                acc[0][3] = fma2(a0, b23.y, acc[0][3]);
                acc[1][0] = fma2(a1, b01.x, acc[1][0]);
                acc[1][1] = fma2(a1, b01.y, acc[1][1]);
                acc[1][2] = fma2(a1, b23.x, acc[1][2]);
                acc[1][3] = fma2(a1, b23.y, acc[1][3]);
                acc[2][0] = fma2(a2, b01.x, acc[2][0]);
                acc[2][1] = fma2(a2, b01.y, acc[2][1]);
                acc[2][2] = fma2(a2, b23.x, acc[2][2]);
                acc[2][3] = fma2(a2, b23.y, acc[2][3]);
                acc[3][0] = fma2(a3, b01.x, acc[3][0]);
                acc[3][1] = fma2(a3, b01.y, acc[3][1]);
                acc[3][2] = fma2(a3, b23.x, acc[3][2]);
                acc[3][3] = fma2(a3, b23.y, acc[3][3]);
            }
            if (!last) {
                buf ^= 1;
                As[buf][kq * 4 + 0][lrow] = aReg.x;
                As[buf][kq * 4 + 1][lrow] = aReg.y;
                As[buf][kq * 4 + 2][lrow] = aReg.z;
                As[buf][kq * 4 + 3][lrow] = aReg.w;
                *(float4*)&Bs[buf][brow][bc] = bReg0;
                *(float4*)&Bs[buf][brow + 8][bc] = bReg1;
                __syncthreads();
            }
        }
    }

    // epilogue: + bias, store (no activation on primary caps)
    const float4 bia0 = *(const float4*)(bias + nbase + tx * 4);
    const float4 bia1 = *(const float4*)(bias + nbase + 64 + tx * 4);
#pragma unroll
    for (int r = 0; r < 4; r++) {
        const int mm = blockIdx.x * 64 + ty * 4 + r;
        const float2 c0 = unpk2(acc[r][0]);
        const float2 c1 = unpk2(acc[r][1]);
        const float2 c2 = unpk2(acc[r][2]);
        const float2 c3 = unpk2(acc[r][3]);
        float4 o0 = make_float4(c0.x + bia0.x, c0.y + bia0.y, c1.x + bia0.z, c1.y + bia0.w);
        float4 o1 = make_float4(c2.x + bia1.x, c2.y + bia1.y, c3.x + bia1.z, c3.y + bia1.w);
        *(float4*)(g_u + (size_t)mm * 256 + nbase + tx * 4) = o0;
        *(float4*)(g_u + (size_t)mm * 256 + nbase + 64 + tx * 4) = o1;
    }
}

// =====================================================================
// Kernel 3: u_hat[b,i,j,k] = sum_m W[i,j,k,m] * u[b,i,m]
// grid 1152 (= i), 256 threads (= b). W[i] slice staged in smem.
// =====================================================================
__global__ __launch_bounds__(256) void uhat_kernel(const float* __restrict__ wp)
{
    __shared__ float Ws[1280];
    const int i = blockIdx.x;
    const int b = threadIdx.x;
    for (int t = threadIdx.x; t < 1280; t += 256) Ws[t] = wp[(size_t)i * 1280 + t];

    const float4* up = (const float4*)(g_u + ((size_t)b * 1152 + i) * 8);
    const float4 u0 = up[0];
    const float4 u1 = up[1];
    __syncthreads();

    float* outp = g_uhat + ((size_t)b * 1152 + i) * 160;
    for (int o = 0; o < 160; o += 4) {
        float4 res;
        float* rp = (float*)&res;
#pragma unroll
        for (int q = 0; q < 4; q++) {
            const float4* wv = (const float4*)&Ws[(o + q) * 8];
            const float4 wa = wv[0];
            const float4 wb = wv[1];
            rp[q] = wa.x * u0.x + wa.y * u0.y + wa.z * u0.z + wa.w * u0.w +
                    wb.x * u1.x + wb.y * u1.y + wb.z * u1.z + wb.w * u1.w;
        }
        *(float4*)(outp + o) = res;
    }
}

// =====================================================================
// Kernel 4: dynamic routing, 3 iterations fused. 1 block per batch elem.
// 320 threads. c in smem (46KB), logits in g_bl. Final v -> d_out, masked v -> g_h0.
// =====================================================================
__global__ __launch_bounds__(320) void routing_kernel(
    const float* __restrict__ y, float* __restrict__ vout)
{
    __shared__ float cb[11520];   // c[i][j]
    __shared__ float sp[320];     // partial s
    __shared__ float vs[160];     // v
    __shared__ float cf[16];      // squash coefficients

    const int b = blockIdx.x;
    const int tid = threadIdx.x;
    const float* uh = g_uhat + (size_t)b * 184320;
    float* bl = g_bl + (size_t)b * 11520;

    const int jk = tid % 160;
    const int h = tid / 160;
    const int jj = jk >> 4;

    for (int r = 0; r < 3; r++) {
        if (r > 0) {
            // softmax over j of bl[i][:]
            for (int i = tid; i < 1152; i += 320) {
                const float* blr = bl + i * 10;
                float xv[10];
#pragma unroll
                for (int j = 0; j < 10; j++) xv[j] = blr[j];
                float mx = xv[0];
#pragma unroll
                for (int j = 1; j < 10; j++) mx = fmaxf(mx, xv[j]);
                float s = 0.f;
#pragma unroll
                for (int j = 0; j < 10; j++) { xv[j] = __expf(xv[j] - mx); s += xv[j]; }
                const float inv = __fdividef(1.f, s);
                float* cr = cb + i * 10;
#pragma unroll
                for (int j = 0; j < 10; j++) cr[j] = xv[j] * inv;
            }
            __syncthreads();
        }
        // s-pass: s[j][k] = sum_i c[i][j] * u_hat[i][j][k]
        float acc = 0.f;
        if (r == 0) {
#pragma unroll 4
            for (int i = h; i < 1152; i += 2) acc += uh[(size_t)i * 160 + jk];
            acc *= 0.1f;
        } else {
#pragma unroll 4
            for (int i = h; i < 1152; i += 2)
                acc += cb[i * 10 + jj] * uh[(size_t)i * 160 + jk];
        }
        sp[tid] = acc;
        __syncthreads();
        if (tid < 160) sp[tid] += sp[tid + 160];
        __syncthreads();
        if (tid < 10) {
            float sn2 = 0.f;
#pragma unroll
            for (int k = 0; k < 16; k++) { const float t = sp[tid * 16 + k]; sn2 += t * t; }
            cf[tid] = sn2 / ((1.f + sn2) * (sqrtf(sn2) + EPSF));
        }
        __syncthreads();
        if (tid < 160) vs[tid] = cf[jj] * sp[tid];
        __syncthreads();
        if (r < 2) {
            // agreement: bl[i][j] += sum_k u_hat[i][j][k]*v[j][k]
            for (int pidx = tid; pidx < 11520; pidx += 320) {
                const int i = pidx / 10;
                const int j = pidx % 10;
                const float4* u4 = (const float4*)(uh + (size_t)i * 160 + j * 16);
                const float4* v4 = (const float4*)(vs + j * 16);
                const float4 a0 = u4[0], a1 = u4[1], a2 = u4[2], a3 = u4[3];
                const float4 w0 = v4[0], w1 = v4[1], w2 = v4[2], w3 = v4[3];
                float d = a0.x * w0.x + a0.y * w0.y + a0.z * w0.z + a0.w * w0.w
                        + a1.x * w1.x + a1.y * w1.y + a1.z * w1.z + a1.w * w1.w
                        + a2.x * w2.x + a2.y * w2.y + a2.z * w2.z + a2.w * w2.w
                        + a3.x * w3.x + a3.y * w3.y + a3.z * w3.z + a3.w * w3.w;
                if (r == 0) bl[pidx] = d;
                else        bl[pidx] += d;
            }
            __syncthreads();
        }
    }
    if (tid < 160) {
        const float v = vs[tid];
        vout[(size_t)b * 160 + tid] = v;                       // output[0]: v
        g_h0[(size_t)b * 160 + tid] = y[b * 10 + jj] * v;      // masked for decoder
    }
}

// =====================================================================
// Kernel 5-7: decoder GEMMs  C = act(A[256,K] @ W[K,N] + bias)
// BM=64 BN=64 BK=16, 256 threads, 4x4 microtile. ACT: 0 relu, 1 sigmoid
// =====================================================================
template <int K, int N, int ACT>
__device__ __forceinline__ void gemm_body(
    const float* __restrict__ A, const float* __restrict__ W,
    const float* __restrict__ bias, float* __restrict__ C)
{
    __shared__ float As[16][68];
    __shared__ float Bs[16][68];
    const int tid = threadIdx.x;
    const int n0 = blockIdx.x * 64;
    const int m0 = blockIdx.y * 64;
    const int ty = tid >> 4, tx = tid & 15;
    const int ar = tid >> 2, ak = (tid & 3) * 4;
    const int bk = tid >> 4, bc = (tid & 15) * 4;

    float acc[4][4];
#pragma unroll
    for (int r = 0; r < 4; r++)
#pragma unroll
        for (int q = 0; q < 4; q++) acc[r][q] = 0.f;

    for (int k0 = 0; k0 < K; k0 += 16) {
        const float4 av = *(const float4*)(A + (size_t)(m0 + ar) * K + k0 + ak);
        float4 bv = make_float4(0.f, 0.f, 0.f, 0.f);
        if (n0 + bc < N) bv = *(const float4*)(W + (size_t)(k0 + bk) * N + n0 + bc);
        __syncthreads();
        As[ak + 0][ar] = av.x;
        As[ak + 1][ar] = av.y;
        As[ak + 2][ar] = av.z;
        As[ak + 3][ar] = av.w;
        *(float4*)&Bs[bk][bc] = bv;
        __syncthreads();
#pragma unroll
        for (int kk = 0; kk < 16; kk++) {
            const float4 a4 = *(const float4*)&As[kk][ty * 4];
            const float4 b4 = *(const float4*)&Bs[kk][tx * 4];
            const float aa[4] = {a4.x, a4.y, a4.z, a4.w};
            const float bb[4] = {b4.x, b4.y, b4.z, b4.w};
#pragma unroll
            for (int r = 0; r < 4; r++)
#pragma unroll
                for (int q = 0; q < 4; q++) acc[r][q] += aa[r] * bb[q];
        }
    }

    if (n0 + tx * 4 < N) {
        const float4 bv = *(const float4*)(bias + n0 + tx * 4);
        const float bb[4] = {bv.x, bv.y, bv.z, bv.w};
#pragma unroll
        for (int r = 0; r < 4; r++) {
            const int mm = m0 + ty * 4 + r;
            float o[4];
#pragma unroll
            for (int q = 0; q < 4; q++) {
                float v = acc[r][q] + bb[q];
                if (ACT == 0) v = fmaxf(v, 0.f);
                else          v = 1.f / (1.f + __expf(-v));
                o[q] = v;
            }
            *(float4*)(C + (size_t)mm * N + n0 + tx * 4) = make_float4(o[0], o[1], o[2], o[3]);
        }
    }
}

__global__ __launch_bounds__(256) void dec1_kernel(const float* __restrict__ W,
                                                   const float* __restrict__ b)
{ gemm_body<160, 512, 0>(g_h0, W, b, g_h1); }

__global__ __launch_bounds__(256) void dec2_kernel(const float* __restrict__ W,
                                                   const float* __restrict__ b)
{ gemm_body<512, 1024, 0>(g_h1, W, b, g_h2); }

__global__ __launch_bounds__(256) void dec3_kernel(const float* __restrict__ W,
                                                   const float* __restrict__ b,
                                                   float* __restrict__ out)
{ gemm_body<1024, 784, 1>(g_h2, W, b, out); }

// =====================================================================
extern "C" void kernel_launch(void* const* d_in, const int* in_sizes, int n_in,
                              void* d_out, int out_size)
{
    const float* input_x = (const float*)d_in[0];
    const float* y       = (const float*)d_in[1];
    const float* conv1_w = (const float*)d_in[2];
    const float* conv1_b = (const float*)d_in[3];
    const float* pc_w    = (const float*)d_in[4];
    const float* pc_b    = (const float*)d_in[5];
    const float* w_pose  = (const float*)d_in[6];
    const float* d1_w    = (const float*)d_in[7];
    const float* d1_b    = (const float*)d_in[8];
    const float* d2_w    = (const float*)d_in[9];
    const float* d2_b    = (const float*)d_in[10];
    const float* d3_w    = (const float*)d_in[11];
    const float* d3_b    = (const float*)d_in[12];
    float* out = (float*)d_out;

    conv1_kernel<<<512, 256>>>(input_x, conv1_w, conv1_b);
    pc_kernel<<<dim3(144, 2), 256>>>(pc_w, pc_b);
    uhat_kernel<<<1152, 256>>>(w_pose);
    routing_kernel<<<BATCH, 320>>>(y, out);              // writes v into out[0 .. 40960)
    dec1_kernel<<<dim3(8, 4), 256>>>(d1_w, d1_b);
    dec2_kernel<<<dim3(16, 4), 256>>>(d2_w, d2_b);
    dec3_kernel<<<dim3(13, 4), 256>>>(d3_w, d3_b, out + BATCH * 160);  // reconstructed
    (void)in_sizes; (void)n_in; (void)out_size;
}

// round 7
// speedup vs baseline: 1.6032x; 1.6032x over previous
#include <cuda_runtime.h>
#include <cuda_bf16.h>
#include <cstdint>
#include <math.h>

#define EPSF 1e-7f
#define BATCH 256

// ---------------- scratch (device globals: no cudaMalloc allowed) ----------------
__device__ __nv_bfloat16 g_x1h[BATCH * 400 * 256];   // conv1 out hi   52 MB
__device__ __nv_bfloat16 g_x1l[BATCH * 400 * 256];   // conv1 out lo   52 MB
__device__ __nv_bfloat16 g_wth[256 * 20736];         // pc weights^T hi
__device__ __nv_bfloat16 g_wtl[256 * 20736];         // pc weights^T lo
__device__ float g_u[9216 * 256];                    // primary caps (fp32)
__device__ float g_uhat[BATCH * 1152 * 160];         // u_hat fp32    189 MB
__device__ float g_h0[BATCH * 160];
__device__ float g_h1[BATCH * 512];
__device__ float g_h2[BATCH * 1024];

// ======================= helpers (all base-sm_100 features) =======================
__device__ __forceinline__ uint32_t smem_u32(const void* p) {
    uint32_t a;
    asm("{ .reg .u64 t; cvta.to.shared.u64 t, %1; cvt.u32.u64 %0, t; }" : "=r"(a) : "l"(p));
    return a;
}
__device__ __forceinline__ void cp16(uint32_t dst, const void* src) {
    asm volatile("cp.async.cg.shared.global [%0], [%1], 16;" :: "r"(dst), "l"(src) : "memory");
}
__device__ __forceinline__ void ldsm4(uint32_t* r, uint32_t addr) {
    asm volatile("ldmatrix.sync.aligned.m8n8.x4.shared.b16 {%0,%1,%2,%3}, [%4];"
                 : "=r"(r[0]), "=r"(r[1]), "=r"(r[2]), "=r"(r[3]) : "r"(addr));
}
__device__ __forceinline__ void mma16816(float* c, const uint32_t* a, const uint32_t* b) {
    asm volatile(
        "mma.sync.aligned.m16n8k16.row.col.f32.bf16.bf16.f32 "
        "{%0,%1,%2,%3}, {%4,%5,%6,%7}, {%8,%9}, {%0,%1,%2,%3};"
        : "+f"(c[0]), "+f"(c[1]), "+f"(c[2]), "+f"(c[3])
        : "r"(a[0]), "r"(a[1]), "r"(a[2]), "r"(a[3]), "r"(b[0]), "r"(b[1]));
}

// =====================================================================
// Kernel 1: conv1 9x9 stride1 + ReLU -> split bf16 hi/lo
// =====================================================================
__global__ __launch_bounds__(256) void conv1_kernel(
    const float* __restrict__ x, const float* __restrict__ w,
    const float* __restrict__ bias)
{
    __shared__ float img[784];
    const int b = blockIdx.x >> 1;
    const int half = blockIdx.x & 1;
    const int c = threadIdx.x;

    for (int t = threadIdx.x; t < 784; t += 256) img[t] = x[b * 784 + t];

    float wr[81];
#pragma unroll
    for (int k = 0; k < 81; k++) wr[k] = w[k * 256 + c];
    const float bv = bias[c];
    __syncthreads();

    const int oy0 = half * 10;
    for (int oy = oy0; oy < oy0 + 10; oy++) {
        for (int ox = 0; ox < 20; ox++) {
            float acc = bv;
            const float* ip = img + oy * 28 + ox;
#pragma unroll
            for (int ky = 0; ky < 9; ky++)
#pragma unroll
                for (int kx = 0; kx < 9; kx++)
                    acc += ip[ky * 28 + kx] * wr[ky * 9 + kx];
            const float v = fmaxf(acc, 0.f);
            const __nv_bfloat16 h = __float2bfloat16(v);
            const size_t off = ((size_t)(b * 20 + oy) * 20 + ox) * 256 + c;
            g_x1h[off] = h;
            g_x1l[off] = __float2bfloat16(v - __bfloat162float(h));
        }
    }
}

// =====================================================================
// Kernel 1b: pc weight transpose + bf16 split: [20736][256] -> [256][20736]
// =====================================================================
__global__ void wtrans_kernel(const float* __restrict__ w)
{
    __shared__ float tile[32][33];
    const int k0 = blockIdx.x * 32, n0 = blockIdx.y * 32;
    const int tx = threadIdx.x, ty = threadIdx.y;
#pragma unroll
    for (int r = 0; r < 4; r++)
        tile[ty + 8 * r][tx] = w[(size_t)(k0 + ty + 8 * r) * 256 + n0 + tx];
    __syncthreads();
#pragma unroll
    for (int r = 0; r < 4; r++) {
        const float v = tile[tx][ty + 8 * r];
        const __nv_bfloat16 h = __float2bfloat16(v);
        const size_t off = (size_t)(n0 + ty + 8 * r) * 20736 + k0 + tx;
        g_wth[off] = h;
        g_wtl[off] = __float2bfloat16(v - __bfloat162float(h));
    }
}

// =====================================================================
// Kernel 2: primary-caps conv — mma.sync bf16 hi/lo GEMM (base sm_100)
// M=9216 N=256 K=20736. BM=128 BN=128 BK=32. 8 warps = 4m x 2n,
// warp tile 32x64 (2 m16 x 8 n8). 3 passes: Ah*Bh + Ah*Bl + Al*Bh.
// Smem row pitch 80B (20-bank rotation/row -> conflict-free ldmatrix).
// =====================================================================
#define PC_STAGE 40960   // Ah(10240) Al(10240) Bh(10240) Bl(10240)

extern __shared__ __align__(128) unsigned char pc_smem[];

__global__ __launch_bounds__(256, 1) void pc_kernel(const float* __restrict__ bias)
{
    const uint32_t sb = smem_u32(pc_smem);
    const int tid = threadIdx.x;
    const int wid = tid >> 5;
    const int lane = tid & 31;
    const int mblock = blockIdx.x * 128;
    const int nbase = blockIdx.y * 128;
    const int warp_m = (wid >> 1) * 32;
    const int warp_n = (wid & 1) * 64;

    // ---- global load mapping: thread handles row r, 32B half `half` ----
    const int r = tid >> 1;
    const int half = tid & 1;
    const int m = mblock + r;
    const int bimg = m / 36, p = m % 36;
    const int aBase = bimg * 102400 + (p / 6) * 10240 + (p % 6) * 512 + half * 16;
    const size_t bBase = (size_t)(nbase + r) * 20736 + half * 16;
    const uint32_t sOff = (uint32_t)(r * 80 + half * 32);

    // ---- ldmatrix per-lane addresses ----
    // A (row-major m16k16): lanes 0-15 rows 0-15 k-chunk kk*2; lanes 16-31 same rows, +16B
    const uint32_t arowoff = (uint32_t)((warp_m + (lane & 15)) * 80 + (lane >> 4) * 16);
    // B (K-major [n][k], col-major operand): mat order n0k0,n0k8,n1k0,n1k8
    const uint32_t browoff = (uint32_t)((warp_n + ((lane >> 4) << 3) + (lane & 7)) * 80 +
                                        ((lane >> 3) & 1) * 16);

    float acc[2][8][4];
#pragma unroll
    for (int mt = 0; mt < 2; mt++)
#pragma unroll
        for (int nt = 0; nt < 8; nt++)
#pragma unroll
            for (int q = 0; q < 4; q++) acc[mt][nt][q] = 0.f;

    // ---- prologue: stage 0 ----
    {
        const uint32_t dst = sb + sOff;
        const __nv_bfloat16* ah = g_x1h + aBase;
        const __nv_bfloat16* al = g_x1l + aBase;
        const __nv_bfloat16* bh = g_wth + bBase;
        const __nv_bfloat16* bl = g_wtl + bBase;
        cp16(dst,            ah); cp16(dst + 16,            ah + 8);
        cp16(dst + 10240,    al); cp16(dst + 10240 + 16,    al + 8);
        cp16(dst + 20480,    bh); cp16(dst + 20480 + 16,    bh + 8);
        cp16(dst + 30720,    bl); cp16(dst + 30720 + 16,    bl + 8);
        asm volatile("cp.async.commit_group;" ::: "memory");
    }

    for (int s = 0; s < 648; s++) {
        if (s + 1 < 648) {
            const int k = (s + 1) * 32;
            const int ky = k / 2304;
            const int dA = ky * 5120 + (k - ky * 2304);
            const uint32_t dst = sb + ((s + 1) & 1) * PC_STAGE + sOff;
            const __nv_bfloat16* ah = g_x1h + aBase + dA;
            const __nv_bfloat16* al = g_x1l + aBase + dA;
            const __nv_bfloat16* bh = g_wth + bBase + k;
            const __nv_bfloat16* bl = g_wtl + bBase + k;
            cp16(dst,         ah); cp16(dst + 16,         ah + 8);
            cp16(dst + 10240, al); cp16(dst + 10240 + 16, al + 8);
            cp16(dst + 20480, bh); cp16(dst + 20480 + 16, bh + 8);
            cp16(dst + 30720, bl); cp16(dst + 30720 + 16, bl + 8);
            asm volatile("cp.async.commit_group;" ::: "memory");
            asm volatile("cp.async.wait_group 1;" ::: "memory");
        } else {
            asm volatile("cp.async.wait_group 0;" ::: "memory");
        }
        __syncthreads();

        const uint32_t Ah = sb + (s & 1) * PC_STAGE;
        const uint32_t Al = Ah + 10240;
        const uint32_t Bh = Ah + 20480;
        const uint32_t Bl = Ah + 30720;

#pragma unroll
        for (int kk = 0; kk < 2; kk++) {
            uint32_t ah[2][4], al[2][4], bh[16], bl[16];
#pragma unroll
            for (int mt = 0; mt < 2; mt++) {
                ldsm4(ah[mt], Ah + arowoff + mt * 1280 + kk * 32);
                ldsm4(al[mt], Al + arowoff + mt * 1280 + kk * 32);
            }
#pragma unroll
            for (int np = 0; np < 4; np++) {
                ldsm4(&bh[np * 4], Bh + browoff + np * 1280 + kk * 32);
                ldsm4(&bl[np * 4], Bl + browoff + np * 1280 + kk * 32);
            }
#pragma unroll
            for (int mt = 0; mt < 2; mt++)
#pragma unroll
                for (int nt = 0; nt < 8; nt++) {
                    float* c = acc[mt][nt];
                    mma16816(c, ah[mt], &bh[nt * 2]);
                    mma16816(c, ah[mt], &bl[nt * 2]);
                    mma16816(c, al[mt], &bh[nt * 2]);
                }
        }
        __syncthreads();   // protect buffer (s&1) before iter s+1 overwrites it
    }

    // ---- epilogue: C fragment layout m16n8 ----
    const int groupID = lane >> 2;
    const int tg = lane & 3;
#pragma unroll
    for (int nt = 0; nt < 8; nt++) {
        const int col = nbase + warp_n + nt * 8 + tg * 2;
        const float b0 = bias[col], b1 = bias[col + 1];
#pragma unroll
        for (int mt = 0; mt < 2; mt++) {
            const int row = mblock + warp_m + mt * 16 + groupID;
            float2 o0 = make_float2(acc[mt][nt][0] + b0, acc[mt][nt][1] + b1);
            float2 o1 = make_float2(acc[mt][nt][2] + b0, acc[mt][nt][3] + b1);
            *(float2*)(g_u + (size_t)row * 256 + col) = o0;
            *(float2*)(g_u + (size_t)(row + 8) * 256 + col) = o1;
        }
    }
}

// =====================================================================
// Kernel 3: u_hat[b,i,jk] = sum_m W[i,jk,m]*u[b,i,m]  (fp32 out)
// =====================================================================
__global__ __launch_bounds__(256) void uhat_kernel(const float* __restrict__ wp)
{
    __shared__ float Ws[1280];
    const int i = blockIdx.x;
    const int b = threadIdx.x;
    for (int t = threadIdx.x; t < 1280; t += 256) Ws[t] = wp[(size_t)i * 1280 + t];

    const float4* up = (const float4*)(g_u + ((size_t)b * 1152 + i) * 8);
    const float4 u0 = up[0];
    const float4 u1 = up[1];
    __syncthreads();

    float* outp = g_uhat + ((size_t)b * 1152 + i) * 160;
    for (int o = 0; o < 160; o += 4) {
        float4 res;
        float* rp = (float*)&res;
#pragma unroll
        for (int q = 0; q < 4; q++) {
            const float4* wv = (const float4*)&Ws[(o + q) * 8];
            const float4 wa = wv[0];
            const float4 wb = wv[1];
            rp[q] = wa.x * u0.x + wa.y * u0.y + wa.z * u0.z + wa.w * u0.w +
                    wb.x * u1.x + wb.y * u1.y + wb.z * u1.z + wb.w * u1.w;
        }
        *(float4*)(outp + o) = res;
    }
}

// =====================================================================
// Kernel 4: routing — 3 fused passes; u_hat read ONCE per iteration.
// b-linearity: logits at iter r = u_hat . (v_0 + ... + v_{r-1}).
// 256 threads = 16 groups (i-strips) x 16 lanes (k).
// =====================================================================
__device__ __forceinline__ void reduce_squash(
    const float acc[10], int tid, int g, int k,
    float red[16][160], float* sbuf, float* coef, float* vdst, float scale)
{
#pragma unroll
    for (int j = 0; j < 10; j++) red[g][j * 16 + k] = acc[j];
    __syncthreads();
    if (tid < 160) {
        float s = 0.f;
#pragma unroll
        for (int g2 = 0; g2 < 16; g2++) s += red[g2][tid];
        sbuf[tid] = s * scale;
    }
    __syncthreads();
    if (tid < 10) {
        float sn2 = 0.f;
#pragma unroll
        for (int kk = 0; kk < 16; kk++) { const float t = sbuf[tid * 16 + kk]; sn2 += t * t; }
        coef[tid] = sn2 / ((1.f + sn2) * (sqrtf(sn2) + EPSF));
    }
    __syncthreads();
    if (tid < 160) vdst[tid] = coef[tid >> 4] * sbuf[tid];
    __syncthreads();
}

__global__ __launch_bounds__(256) void routing_kernel(
    const float* __restrict__ y, float* __restrict__ vout)
{
    __shared__ float red[16][160];
    __shared__ float sbuf[160];
    __shared__ float coef[10];
    __shared__ float v0[160];
    __shared__ float vcur[160];

    const int b = blockIdx.x;
    const int tid = threadIdx.x;
    const int g = tid >> 4, k = tid & 15;
    const float* uh = g_uhat + (size_t)b * 184320;

    float acc[10];

    // ---- pass A: uniform c = 0.1 ----
#pragma unroll
    for (int j = 0; j < 10; j++) acc[j] = 0.f;
    for (int i = g; i < 1152; i += 16) {
        const float* r = uh + (size_t)i * 160 + k;
#pragma unroll
        for (int j = 0; j < 10; j++) acc[j] += r[j * 16];
    }
    reduce_squash(acc, tid, g, k, red, sbuf, coef, v0, 0.1f);
    if (tid < 160) vcur[tid] = v0[tid];
    __syncthreads();

    // ---- pass B (logits = u.v0) and pass C (logits = u.(v0+v1)) ----
    for (int pass = 0; pass < 2; pass++) {
        float vr[10];
#pragma unroll
        for (int j = 0; j < 10; j++) vr[j] = vcur[j * 16 + k];
#pragma unroll
        for (int j = 0; j < 10; j++) acc[j] = 0.f;

        for (int i = g; i < 1152; i += 16) {
            const float* r = uh + (size_t)i * 160 + k;
            float u[10], a[10];
#pragma unroll
            for (int j = 0; j < 10; j++) u[j] = r[j * 16];
#pragma unroll
            for (int j = 0; j < 10; j++) {
                float d = u[j] * vr[j];
                d += __shfl_xor_sync(0xffffffffu, d, 1);
                d += __shfl_xor_sync(0xffffffffu, d, 2);
                d += __shfl_xor_sync(0xffffffffu, d, 4);
                d += __shfl_xor_sync(0xffffffffu, d, 8);
                a[j] = d;
            }
            float mx = a[0];
#pragma unroll
            for (int j = 1; j < 10; j++) mx = fmaxf(mx, a[j]);
            float sum = 0.f;
#pragma unroll
            for (int j = 0; j < 10; j++) { a[j] = __expf(a[j] - mx); sum += a[j]; }
            const float inv = __fdividef(1.f, sum);
#pragma unroll
            for (int j = 0; j < 10; j++) acc[j] += a[j] * inv * u[j];
        }
        reduce_squash(acc, tid, g, k, red, sbuf, coef, vcur, 1.f);
        if (pass == 0) {
            if (tid < 160) vcur[tid] += v0[tid];   // v0 + v1 for pass C logits
            __syncthreads();
        }
    }

    if (tid < 160) {
        const float v = vcur[tid];
        vout[(size_t)b * 160 + tid] = v;
        g_h0[(size_t)b * 160 + tid] = y[b * 10 + (tid >> 4)] * v;
    }
}

// =====================================================================
// Kernel 5-7: decoder GEMMs
// =====================================================================
template <int K, int N, int ACT>
__device__ __forceinline__ void gemm_body(
    const float* __restrict__ A, const float* __restrict__ W,
    const float* __restrict__ bias, float* __restrict__ C)
{
    __shared__ float As[16][68];
    __shared__ float Bs[16][68];
    const int tid = threadIdx.x;
    const int n0 = blockIdx.x * 64;
    const int m0 = blockIdx.y * 64;
    const int ty = tid >> 4, tx = tid & 15;
    const int ar = tid >> 2, ak = (tid & 3) * 4;
    const int bk = tid >> 4, bc = (tid & 15) * 4;

    float acc[4][4];
#pragma unroll
    for (int r = 0; r < 4; r++)
#pragma unroll
        for (int q = 0; q < 4; q++) acc[r][q] = 0.f;

    for (int k0 = 0; k0 < K; k0 += 16) {
        const float4 av = *(const float4*)(A + (size_t)(m0 + ar) * K + k0 + ak);
        float4 bv = make_float4(0.f, 0.f, 0.f, 0.f);
        if (n0 + bc < N) bv = *(const float4*)(W + (size_t)(k0 + bk) * N + n0 + bc);
        __syncthreads();
        As[ak + 0][ar] = av.x;
        As[ak + 1][ar] = av.y;
        As[ak + 2][ar] = av.z;
        As[ak + 3][ar] = av.w;
        *(float4*)&Bs[bk][bc] = bv;
        __syncthreads();
#pragma unroll
        for (int kk = 0; kk < 16; kk++) {
            const float4 a4 = *(const float4*)&As[kk][ty * 4];
            const float4 b4 = *(const float4*)&Bs[kk][tx * 4];
            const float aa[4] = {a4.x, a4.y, a4.z, a4.w};
            const float bb[4] = {b4.x, b4.y, b4.z, b4.w};
#pragma unroll
            for (int r = 0; r < 4; r++)
#pragma unroll
                for (int q = 0; q < 4; q++) acc[r][q] += aa[r] * bb[q];
        }
    }

    if (n0 + tx * 4 < N) {
        const float4 bv = *(const float4*)(bias + n0 + tx * 4);
        const float bb[4] = {bv.x, bv.y, bv.z, bv.w};
#pragma unroll
        for (int r = 0; r < 4; r++) {
            const int mm = m0 + ty * 4 + r;
            float o[4];
#pragma unroll
            for (int q = 0; q < 4; q++) {
                float v = acc[r][q] + bb[q];
                if (ACT == 0) v = fmaxf(v, 0.f);
                else          v = 1.f / (1.f + __expf(-v));
                o[q] = v;
            }
            *(float4*)(C + (size_t)mm * N + n0 + tx * 4) = make_float4(o[0], o[1], o[2], o[3]);
        }
    }
}

__global__ __launch_bounds__(256) void dec1_kernel(const float* __restrict__ W,
                                                   const float* __restrict__ b)
{ gemm_body<160, 512, 0>(g_h0, W, b, g_h1); }

__global__ __launch_bounds__(256) void dec2_kernel(const float* __restrict__ W,
                                                   const float* __restrict__ b)
{ gemm_body<512, 1024, 0>(g_h1, W, b, g_h2); }

__global__ __launch_bounds__(256) void dec3_kernel(const float* __restrict__ W,
                                                   const float* __restrict__ b,
                                                   float* __restrict__ out)
{ gemm_body<1024, 784, 1>(g_h2, W, b, out); }

// =====================================================================
extern "C" void kernel_launch(void* const* d_in, const int* in_sizes, int n_in,
                              void* d_out, int out_size)
{
    const float* input_x = (const float*)d_in[0];
    const float* y       = (const float*)d_in[1];
    const float* conv1_w = (const float*)d_in[2];
    const float* conv1_b = (const float*)d_in[3];
    const float* pc_w    = (const float*)d_in[4];
    const float* pc_b    = (const float*)d_in[5];
    const float* w_pose  = (const float*)d_in[6];
    const float* d1_w    = (const float*)d_in[7];
    const float* d1_b    = (const float*)d_in[8];
    const float* d2_w    = (const float*)d_in[9];
    const float* d2_b    = (const float*)d_in[10];
    const float* d3_w    = (const float*)d_in[11];
    const float* d3_b    = (const float*)d_in[12];
    float* out = (float*)d_out;

    // Unconditional (no static guard per harness rules); idempotent + capture-safe.
    cudaFuncSetAttribute(pc_kernel, cudaFuncAttributeMaxDynamicSharedMemorySize, 2 * PC_STAGE);

    wtrans_kernel<<<dim3(648, 8), dim3(32, 8)>>>(pc_w);
    conv1_kernel<<<512, 256>>>(input_x, conv1_w, conv1_b);
    pc_kernel<<<dim3(72, 2), 256, 2 * PC_STAGE>>>(pc_b);
    uhat_kernel<<<1152, 256>>>(w_pose);
    routing_kernel<<<BATCH, 256>>>(y, out);
    dec1_kernel<<<dim3(8, 4), 256>>>(d1_w, d1_b);
    dec2_kernel<<<dim3(16, 4), 256>>>(d2_w, d2_b);
    dec3_kernel<<<dim3(13, 4), 256>>>(d3_w, d3_b, out + BATCH * 160);
    (void)in_sizes; (void)n_in; (void)out_size;
}

// round 8
// speedup vs baseline: 1.7312x; 1.0799x over previous
#include <cuda_runtime.h>
#include <cuda_bf16.h>
#include <cstdint>
#include <math.h>

#define EPSF 1e-7f
#define BATCH 256

// ---------------- scratch (device globals: no cudaMalloc allowed) ----------------
__device__ __nv_bfloat16 g_x1h[BATCH * 400 * 256];   // conv1 out hi   52 MB
__device__ __nv_bfloat16 g_x1l[BATCH * 400 * 256];   // conv1 out lo   52 MB
__device__ __nv_bfloat16 g_wth[256 * 20736];         // pc weights^T hi
__device__ __nv_bfloat16 g_wtl[256 * 20736];         // pc weights^T lo
__device__ float g_u[9216 * 256];                    // primary caps (fp32)
__device__ float g_uhat[BATCH * 1152 * 160];         // u_hat fp32    189 MB
__device__ float g_h0[BATCH * 160];
__device__ float g_h1[BATCH * 512];
__device__ float g_h2[BATCH * 1024];

// ======================= helpers (all base-sm_100 features) =======================
__device__ __forceinline__ uint32_t smem_u32(const void* p) {
    uint32_t a;
    asm("{ .reg .u64 t; cvta.to.shared.u64 t, %1; cvt.u32.u64 %0, t; }" : "=r"(a) : "l"(p));
    return a;
}
__device__ __forceinline__ void cp16(uint32_t dst, const void* src) {
    asm volatile("cp.async.cg.shared.global [%0], [%1], 16;" :: "r"(dst), "l"(src) : "memory");
}
__device__ __forceinline__ void ldsm4(uint32_t* r, uint32_t addr) {
    asm volatile("ldmatrix.sync.aligned.m8n8.x4.shared.b16 {%0,%1,%2,%3}, [%4];"
                 : "=r"(r[0]), "=r"(r[1]), "=r"(r[2]), "=r"(r[3]) : "r"(addr));
}
__device__ __forceinline__ void mma16816(float* c, const uint32_t* a, const uint32_t* b) {
    asm volatile(
        "mma.sync.aligned.m16n8k16.row.col.f32.bf16.bf16.f32 "
        "{%0,%1,%2,%3}, {%4,%5,%6,%7}, {%8,%9}, {%0,%1,%2,%3};"
        : "+f"(c[0]), "+f"(c[1]), "+f"(c[2]), "+f"(c[3])
        : "r"(a[0]), "r"(a[1]), "r"(a[2]), "r"(a[3]), "r"(b[0]), "r"(b[1]));
}

// =====================================================================
// Kernel 1: conv1 9x9 stride1 + ReLU -> split bf16 hi/lo
// =====================================================================
__global__ __launch_bounds__(256) void conv1_kernel(
    const float* __restrict__ x, const float* __restrict__ w,
    const float* __restrict__ bias)
{
    __shared__ float img[784];
    const int b = blockIdx.x >> 1;
    const int half = blockIdx.x & 1;
    const int c = threadIdx.x;

    for (int t = threadIdx.x; t < 784; t += 256) img[t] = x[b * 784 + t];

    float wr[81];
#pragma unroll
    for (int k = 0; k < 81; k++) wr[k] = w[k * 256 + c];
    const float bv = bias[c];
    __syncthreads();

    const int oy0 = half * 10;
    for (int oy = oy0; oy < oy0 + 10; oy++) {
        for (int ox = 0; ox < 20; ox++) {
            float acc = bv;
            const float* ip = img + oy * 28 + ox;
#pragma unroll
            for (int ky = 0; ky < 9; ky++)
#pragma unroll
                for (int kx = 0; kx < 9; kx++)
                    acc += ip[ky * 28 + kx] * wr[ky * 9 + kx];
            const float v = fmaxf(acc, 0.f);
            const __nv_bfloat16 h = __float2bfloat16(v);
            const size_t off = ((size_t)(b * 20 + oy) * 20 + ox) * 256 + c;
            g_x1h[off] = h;
            g_x1l[off] = __float2bfloat16(v - __bfloat162float(h));
        }
    }
}

// =====================================================================
// Kernel 1b: pc weight transpose + bf16 split: [20736][256] -> [256][20736]
// =====================================================================
__global__ void wtrans_kernel(const float* __restrict__ w)
{
    __shared__ float tile[32][33];
    const int k0 = blockIdx.x * 32, n0 = blockIdx.y * 32;
    const int tx = threadIdx.x, ty = threadIdx.y;
#pragma unroll
    for (int r = 0; r < 4; r++)
        tile[ty + 8 * r][tx] = w[(size_t)(k0 + ty + 8 * r) * 256 + n0 + tx];
    __syncthreads();
#pragma unroll
    for (int r = 0; r < 4; r++) {
        const float v = tile[tx][ty + 8 * r];
        const __nv_bfloat16 h = __float2bfloat16(v);
        const size_t off = (size_t)(n0 + ty + 8 * r) * 20736 + k0 + tx;
        g_wth[off] = h;
        g_wtl[off] = __float2bfloat16(v - __bfloat162float(h));
    }
}

// =====================================================================
// Kernel 2: primary-caps conv — mma.sync bf16 hi/lo GEMM, 3-stage pipeline.
// M=9216 N=256 K=20736. BM=128 BN=128 BK=32. 8 warps = 4m x 2n,
// warp tile 32x64. 3 passes: Ah*Bh + Ah*Bl + Al*Bh.
// Smem row pitch 80B (20-bank rotation/row -> conflict-free ldmatrix).
// =====================================================================
#define PC_STAGE 40960   // Ah(10240) Al(10240) Bh(10240) Bl(10240)
#define PC_NSTAGE 3

#define PC_ISSUE(s_) do {                                                   \
    const int k_ = (s_) * 32;                                               \
    const int ky_ = k_ / 2304;                                              \
    const int dA_ = ky_ * 5120 + (k_ - ky_ * 2304);                         \
    const uint32_t dst_ = sb + ((s_) % PC_NSTAGE) * PC_STAGE + sOff;        \
    const __nv_bfloat16* ah_ = g_x1h + aBase + dA_;                         \
    const __nv_bfloat16* al_ = g_x1l + aBase + dA_;                         \
    const __nv_bfloat16* bh_ = g_wth + bBase + k_;                          \
    const __nv_bfloat16* bl_ = g_wtl + bBase + k_;                          \
    cp16(dst_,              ah_); cp16(dst_ + 16,         ah_ + 8);         \
    cp16(dst_ + 10240,      al_); cp16(dst_ + 10240 + 16, al_ + 8);         \
    cp16(dst_ + 20480,      bh_); cp16(dst_ + 20480 + 16, bh_ + 8);         \
    cp16(dst_ + 30720,      bl_); cp16(dst_ + 30720 + 16, bl_ + 8);         \
} while (0)

extern __shared__ __align__(128) unsigned char pc_smem[];

__global__ __launch_bounds__(256, 1) void pc_kernel(const float* __restrict__ bias)
{
    const uint32_t sb = smem_u32(pc_smem);
    const int tid = threadIdx.x;
    const int wid = tid >> 5;
    const int lane = tid & 31;
    const int mblock = blockIdx.x * 128;
    const int nbase = blockIdx.y * 128;
    const int warp_m = (wid >> 1) * 32;
    const int warp_n = (wid & 1) * 64;

    // ---- global load mapping: thread handles row r, 32B half ----
    const int r = tid >> 1;
    const int half = tid & 1;
    const int m = mblock + r;
    const int bimg = m / 36, p = m % 36;
    const int aBase = bimg * 102400 + (p / 6) * 10240 + (p % 6) * 512 + half * 16;
    const size_t bBase = (size_t)(nbase + r) * 20736 + half * 16;
    const uint32_t sOff = (uint32_t)(r * 80 + half * 32);

    // ---- ldmatrix per-lane addresses ----
    const uint32_t arowoff = (uint32_t)((warp_m + (lane & 15)) * 80 + (lane >> 4) * 16);
    const uint32_t browoff = (uint32_t)((warp_n + ((lane >> 4) << 3) + (lane & 7)) * 80 +
                                        ((lane >> 3) & 1) * 16);

    float acc[2][8][4];
#pragma unroll
    for (int mt = 0; mt < 2; mt++)
#pragma unroll
        for (int nt = 0; nt < 8; nt++)
#pragma unroll
            for (int q = 0; q < 4; q++) acc[mt][nt][q] = 0.f;

    // ---- prologue: stages 0, 1 ----
    PC_ISSUE(0);
    asm volatile("cp.async.commit_group;" ::: "memory");
    PC_ISSUE(1);
    asm volatile("cp.async.commit_group;" ::: "memory");

    for (int s = 0; s < 648; s++) {
        if (s + 2 < 648) PC_ISSUE(s + 2);
        asm volatile("cp.async.commit_group;" ::: "memory");
        asm volatile("cp.async.wait_group 2;" ::: "memory");   // stage s resident
        __syncthreads();

        const uint32_t Ah = sb + (s % PC_NSTAGE) * PC_STAGE;
        const uint32_t Al = Ah + 10240;
        const uint32_t Bh = Ah + 20480;
        const uint32_t Bl = Ah + 30720;

#pragma unroll
        for (int kk = 0; kk < 2; kk++) {
            uint32_t ah[2][4], al[2][4], bh[16], bl[16];
#pragma unroll
            for (int mt = 0; mt < 2; mt++) {
                ldsm4(ah[mt], Ah + arowoff + mt * 1280 + kk * 32);
                ldsm4(al[mt], Al + arowoff + mt * 1280 + kk * 32);
            }
#pragma unroll
            for (int np = 0; np < 4; np++) {
                ldsm4(&bh[np * 4], Bh + browoff + np * 1280 + kk * 32);
                ldsm4(&bl[np * 4], Bl + browoff + np * 1280 + kk * 32);
            }
#pragma unroll
            for (int mt = 0; mt < 2; mt++)
#pragma unroll
                for (int nt = 0; nt < 8; nt++) {
                    float* c = acc[mt][nt];
                    mma16816(c, ah[mt], &bh[nt * 2]);
                    mma16816(c, ah[mt], &bl[nt * 2]);
                    mma16816(c, al[mt], &bh[nt * 2]);
                }
        }
        __syncthreads();   // all warps done reading buf (s%3) before it is re-filled
    }

    // ---- epilogue: C fragment layout m16n8 ----
    const int groupID = lane >> 2;
    const int tg = lane & 3;
#pragma unroll
    for (int nt = 0; nt < 8; nt++) {
        const int col = nbase + warp_n + nt * 8 + tg * 2;
        const float b0 = bias[col], b1 = bias[col + 1];
#pragma unroll
        for (int mt = 0; mt < 2; mt++) {
            const int row = mblock + warp_m + mt * 16 + groupID;
            float2 o0 = make_float2(acc[mt][nt][0] + b0, acc[mt][nt][1] + b1);
            float2 o1 = make_float2(acc[mt][nt][2] + b0, acc[mt][nt][3] + b1);
            *(float2*)(g_u + (size_t)row * 256 + col) = o0;
            *(float2*)(g_u + (size_t)(row + 8) * 256 + col) = o1;
        }
    }
}

// =====================================================================
// Kernel 3: u_hat[b,i,jk] = sum_m W[i,jk,m]*u[b,i,m]  (fp32 out)
// grid=1152 (i). 320 threads = 8 b-lanes x 40 jk-groups (4 jk each).
// Coalesced STG.128 per (b,i); u loads are warp broadcasts.
// =====================================================================
__global__ __launch_bounds__(320) void uhat_kernel(const float* __restrict__ wp)
{
    __shared__ float Ws[1280];
    const int i = blockIdx.x;
    const int tid = threadIdx.x;
    for (int t = tid; t < 1280; t += 320) Ws[t] = wp[(size_t)i * 1280 + t];
    __syncthreads();

    const int blane = tid / 40;        // 0..7
    const int jkg = tid - blane * 40;  // 0..39

    float w[32];
#pragma unroll
    for (int q = 0; q < 4; q++)
#pragma unroll
        for (int mm = 0; mm < 8; mm++) w[q * 8 + mm] = Ws[(jkg * 4 + q) * 8 + mm];

    const float* ubase = g_u + (size_t)i * 8;               // + b*9216
    float* obase = g_uhat + (size_t)i * 160 + jkg * 4;      // + b*184320

    for (int it = 0; it < 32; it++) {
        const int b = it * 8 + blane;
        const float4 u0 = *(const float4*)(ubase + (size_t)b * 9216);
        const float4 u1 = *(const float4*)(ubase + (size_t)b * 9216 + 4);
        float4 res;
        float* rp = (float*)&res;
#pragma unroll
        for (int q = 0; q < 4; q++) {
            const float* wq = w + q * 8;
            rp[q] = wq[0] * u0.x + wq[1] * u0.y + wq[2] * u0.z + wq[3] * u0.w +
                    wq[4] * u1.x + wq[5] * u1.y + wq[6] * u1.z + wq[7] * u1.w;
        }
        *(float4*)(obase + (size_t)b * 184320) = res;
    }
}

// =====================================================================
// Kernel 4: routing — 3 fused passes; u_hat read ONCE per iteration.
// b-linearity: logits at iter r = u_hat . (v_0 + ... + v_{r-1}).
// =====================================================================
__device__ __forceinline__ void reduce_squash(
    const float acc[10], int tid, int g, int k,
    float red[16][160], float* sbuf, float* coef, float* vdst, float scale)
{
#pragma unroll
    for (int j = 0; j < 10; j++) red[g][j * 16 + k] = acc[j];
    __syncthreads();
    if (tid < 160) {
        float s = 0.f;
#pragma unroll
        for (int g2 = 0; g2 < 16; g2++) s += red[g2][tid];
        sbuf[tid] = s * scale;
    }
    __syncthreads();
    if (tid < 10) {
        float sn2 = 0.f;
#pragma unroll
        for (int kk = 0; kk < 16; kk++) { const float t = sbuf[tid * 16 + kk]; sn2 += t * t; }
        coef[tid] = sn2 / ((1.f + sn2) * (sqrtf(sn2) + EPSF));
    }
    __syncthreads();
    if (tid < 160) vdst[tid] = coef[tid >> 4] * sbuf[tid];
    __syncthreads();
}

__global__ __launch_bounds__(256) void routing_kernel(
    const float* __restrict__ y, float* __restrict__ vout)
{
    __shared__ float red[16][160];
    __shared__ float sbuf[160];
    __shared__ float coef[10];
    __shared__ float v0[160];
    __shared__ float vcur[160];

    const int b = blockIdx.x;
    const int tid = threadIdx.x;
    const int g = tid >> 4, k = tid & 15;
    const float* uh = g_uhat + (size_t)b * 184320;

    float acc[10];

#pragma unroll
    for (int j = 0; j < 10; j++) acc[j] = 0.f;
    for (int i = g; i < 1152; i += 16) {
        const float* r = uh + (size_t)i * 160 + k;
#pragma unroll
        for (int j = 0; j < 10; j++) acc[j] += r[j * 16];
    }
    reduce_squash(acc, tid, g, k, red, sbuf, coef, v0, 0.1f);
    if (tid < 160) vcur[tid] = v0[tid];
    __syncthreads();

    for (int pass = 0; pass < 2; pass++) {
        float vr[10];
#pragma unroll
        for (int j = 0; j < 10; j++) vr[j] = vcur[j * 16 + k];
#pragma unroll
        for (int j = 0; j < 10; j++) acc[j] = 0.f;

        for (int i = g; i < 1152; i += 16) {
            const float* r = uh + (size_t)i * 160 + k;
            float u[10], a[10];
#pragma unroll
            for (int j = 0; j < 10; j++) u[j] = r[j * 16];
#pragma unroll
            for (int j = 0; j < 10; j++) {
                float d = u[j] * vr[j];
                d += __shfl_xor_sync(0xffffffffu, d, 1);
                d += __shfl_xor_sync(0xffffffffu, d, 2);
                d += __shfl_xor_sync(0xffffffffu, d, 4);
                d += __shfl_xor_sync(0xffffffffu, d, 8);
                a[j] = d;
            }
            float mx = a[0];
#pragma unroll
            for (int j = 1; j < 10; j++) mx = fmaxf(mx, a[j]);
            float sum = 0.f;
#pragma unroll
            for (int j = 0; j < 10; j++) { a[j] = __expf(a[j] - mx); sum += a[j]; }
            const float inv = __fdividef(1.f, sum);
#pragma unroll
            for (int j = 0; j < 10; j++) acc[j] += a[j] * inv * u[j];
        }
        reduce_squash(acc, tid, g, k, red, sbuf, coef, vcur, 1.f);
        if (pass == 0) {
            if (tid < 160) vcur[tid] += v0[tid];
            __syncthreads();
        }
    }

    if (tid < 160) {
        const float v = vcur[tid];
        vout[(size_t)b * 160 + tid] = v;
        g_h0[(size_t)b * 160 + tid] = y[b * 10 + (tid >> 4)] * v;
    }
}

// =====================================================================
// Kernel 5-7: decoder GEMMs
// =====================================================================
template <int K, int N, int ACT>
__device__ __forceinline__ void gemm_body(
    const float* __restrict__ A, const float* __restrict__ W,
    const float* __restrict__ bias, float* __restrict__ C)
{
    __shared__ float As[16][68];
    __shared__ float Bs[16][68];
    const int tid = threadIdx.x;
    const int n0 = blockIdx.x * 64;
    const int m0 = blockIdx.y * 64;
    const int ty = tid >> 4, tx = tid & 15;
    const int ar = tid >> 2, ak = (tid & 3) * 4;
    const int bk = tid >> 4, bc = (tid & 15) * 4;

    float acc[4][4];
#pragma unroll
    for (int r = 0; r < 4; r++)
#pragma unroll
        for (int q = 0; q < 4; q++) acc[r][q] = 0.f;

    for (int k0 = 0; k0 < K; k0 += 16) {
        const float4 av = *(const float4*)(A + (size_t)(m0 + ar) * K + k0 + ak);
        float4 bv = make_float4(0.f, 0.f, 0.f, 0.f);
        if (n0 + bc < N) bv = *(const float4*)(W + (size_t)(k0 + bk) * N + n0 + bc);
        __syncthreads();
        As[ak + 0][ar] = av.x;
        As[ak + 1][ar] = av.y;
        As[ak + 2][ar] = av.z;
        As[ak + 3][ar] = av.w;
        *(float4*)&Bs[bk][bc] = bv;
        __syncthreads();
#pragma unroll
        for (int kk = 0; kk < 16; kk++) {
            const float4 a4 = *(const float4*)&As[kk][ty * 4];
            const float4 b4 = *(const float4*)&Bs[kk][tx * 4];
            const float aa[4] = {a4.x, a4.y, a4.z, a4.w};
            const float bb[4] = {b4.x, b4.y, b4.z, b4.w};
#pragma unroll
            for (int r = 0; r < 4; r++)
#pragma unroll
                for (int q = 0; q < 4; q++) acc[r][q] += aa[r] * bb[q];
        }
    }

    if (n0 + tx * 4 < N) {
        const float4 bv = *(const float4*)(bias + n0 + tx * 4);
        const float bb[4] = {bv.x, bv.y, bv.z, bv.w};
#pragma unroll
        for (int r = 0; r < 4; r++) {
            const int mm = m0 + ty * 4 + r;
            float o[4];
#pragma unroll
            for (int q = 0; q < 4; q++) {
                float v = acc[r][q] + bb[q];
                if (ACT == 0) v = fmaxf(v, 0.f);
                else          v = 1.f / (1.f + __expf(-v));
                o[q] = v;
            }
            *(float4*)(C + (size_t)mm * N + n0 + tx * 4) = make_float4(o[0], o[1], o[2], o[3]);
        }
    }
}

__global__ __launch_bounds__(256) void dec1_kernel(const float* __restrict__ W,
                                                   const float* __restrict__ b)
{ gemm_body<160, 512, 0>(g_h0, W, b, g_h1); }

__global__ __launch_bounds__(256) void dec2_kernel(const float* __restrict__ W,
                                                   const float* __restrict__ b)
{ gemm_body<512, 1024, 0>(g_h1, W, b, g_h2); }

__global__ __launch_bounds__(256) void dec3_kernel(const float* __restrict__ W,
                                                   const float* __restrict__ b,
                                                   float* __restrict__ out)
{ gemm_body<1024, 784, 1>(g_h2, W, b, out); }

// =====================================================================
extern "C" void kernel_launch(void* const* d_in, const int* in_sizes, int n_in,
                              void* d_out, int out_size)
{
    const float* input_x = (const float*)d_in[0];
    const float* y       = (const float*)d_in[1];
    const float* conv1_w = (const float*)d_in[2];
    const float* conv1_b = (const float*)d_in[3];
    const float* pc_w    = (const float*)d_in[4];
    const float* pc_b    = (const float*)d_in[5];
    const float* w_pose  = (const float*)d_in[6];
    const float* d1_w    = (const float*)d_in[7];
    const float* d1_b    = (const float*)d_in[8];
    const float* d2_w    = (const float*)d_in[9];
    const float* d2_b    = (const float*)d_in[10];
    const float* d3_w    = (const float*)d_in[11];
    const float* d3_b    = (const float*)d_in[12];
    float* out = (float*)d_out;

    cudaFuncSetAttribute(pc_kernel, cudaFuncAttributeMaxDynamicSharedMemorySize,
                         PC_NSTAGE * PC_STAGE);

    wtrans_kernel<<<dim3(648, 8), dim3(32, 8)>>>(pc_w);
    conv1_kernel<<<512, 256>>>(input_x, conv1_w, conv1_b);
    pc_kernel<<<dim3(72, 2), 256, PC_NSTAGE * PC_STAGE>>>(pc_b);
    uhat_kernel<<<1152, 320>>>(w_pose);
    routing_kernel<<<BATCH, 256>>>(y, out);
    dec1_kernel<<<dim3(8, 4), 256>>>(d1_w, d1_b);
    dec2_kernel<<<dim3(16, 4), 256>>>(d2_w, d2_b);
    dec3_kernel<<<dim3(13, 4), 256>>>(d3_w, d3_b, out + BATCH * 160);
    (void)in_sizes; (void)n_in; (void)out_size;
}

// round 9
// speedup vs baseline: 2.2478x; 1.2984x over previous
#include <cuda_runtime.h>
#include <cuda_bf16.h>
#include <cstdint>
#include <math.h>

#define EPSF 1e-7f
#define BATCH 256

// ---------------- scratch (device globals: no cudaMalloc allowed) ----------------
__device__ float g_x1f[BATCH * 400 * 256];            // conv1 out fp32  105 MB
__device__ signed char g_xq1[BATCH * 400 * 256];      // conv1 digit1 (int8)
__device__ signed char g_xq2[BATCH * 400 * 256];      // conv1 digit2
__device__ signed char g_wq1[256 * 20736];            // pc weights^T digit1
__device__ signed char g_wq2[256 * 20736];            // pc weights^T digit2
__device__ unsigned g_maxA_bits, g_maxB_bits;
__device__ float g_u[9216 * 256];                     // primary caps (fp32)
__device__ float g_uhat[BATCH * 1152 * 160];          // u_hat fp32   189 MB
__device__ float g_h0[BATCH * 160];
__device__ float g_h1[BATCH * 512];
__device__ float g_h2[BATCH * 1024];

// ======================= helpers (base-sm_100 features only) =======================
__device__ __forceinline__ uint32_t smem_u32(const void* p) {
    uint32_t a;
    asm("{ .reg .u64 t; cvta.to.shared.u64 t, %1; cvt.u32.u64 %0, t; }" : "=r"(a) : "l"(p));
    return a;
}
__device__ __forceinline__ void cp16(uint32_t dst, const void* src) {
    asm volatile("cp.async.cg.shared.global [%0], [%1], 16;" :: "r"(dst), "l"(src) : "memory");
}
__device__ __forceinline__ void mma_s8(int* c, const int* a, int b0, int b1) {
    asm volatile(
        "mma.sync.aligned.m16n8k32.row.col.s32.s8.s8.s32 "
        "{%0,%1,%2,%3}, {%4,%5,%6,%7}, {%8,%9}, {%0,%1,%2,%3};"
        : "+r"(c[0]), "+r"(c[1]), "+r"(c[2]), "+r"(c[3])
        : "r"(a[0]), "r"(a[1]), "r"(a[2]), "r"(a[3]), "r"(b0), "r"(b1));
}

// =====================================================================
// Kernel 0: reset per-launch reductions
// =====================================================================
__global__ void init_kernel() { g_maxA_bits = 0u; g_maxB_bits = 0u; }

// =====================================================================
// Kernel 1: conv1 9x9 stride1 + ReLU -> fp32 + global max (atomicMax on bits)
// =====================================================================
__global__ __launch_bounds__(256) void conv1_kernel(
    const float* __restrict__ x, const float* __restrict__ w,
    const float* __restrict__ bias)
{
    __shared__ float img[784];
    const int b = blockIdx.x >> 1;
    const int half = blockIdx.x & 1;
    const int c = threadIdx.x;

    for (int t = threadIdx.x; t < 784; t += 256) img[t] = x[b * 784 + t];

    float wr[81];
#pragma unroll
    for (int k = 0; k < 81; k++) wr[k] = w[k * 256 + c];
    const float bv = bias[c];
    __syncthreads();

    float lmax = 0.f;
    const int oy0 = half * 10;
    for (int oy = oy0; oy < oy0 + 10; oy++) {
        for (int ox = 0; ox < 20; ox++) {
            float acc = bv;
            const float* ip = img + oy * 28 + ox;
#pragma unroll
            for (int ky = 0; ky < 9; ky++)
#pragma unroll
                for (int kx = 0; kx < 9; kx++)
                    acc += ip[ky * 28 + kx] * wr[ky * 9 + kx];
            const float v = fmaxf(acc, 0.f);
            lmax = fmaxf(lmax, v);
            g_x1f[((size_t)(b * 20 + oy) * 20 + ox) * 256 + c] = v;
        }
    }
    atomicMax(&g_maxA_bits, __float_as_uint(lmax));   // v >= 0: bit order == float order
}

// =====================================================================
// Kernel 1b: max |w| of pc weights
// =====================================================================
__global__ __launch_bounds__(256) void maxB_kernel(const float* __restrict__ w)
{
    float lmax = 0.f;
    for (size_t i = (size_t)blockIdx.x * 2048 + threadIdx.x * 8;
         i < (size_t)(blockIdx.x + 1) * 2048 * 0 + (size_t)blockIdx.x * 2048 + threadIdx.x * 8 + 8; i++)
        ; // (placeholder removed below)
    // strided loop over 5,308,416 elements
    for (size_t i = (size_t)blockIdx.x * blockDim.x + threadIdx.x; i < 5308416u;
         i += (size_t)gridDim.x * blockDim.x)
        lmax = fmaxf(lmax, fabsf(w[i]));
    atomicMax(&g_maxB_bits, __float_as_uint(lmax));
}

// =====================================================================
// Kernel 1c: quantize conv1 output -> two int8 digits (base 128)
// =====================================================================
__global__ __launch_bounds__(256) void quantA_kernel()
{
    const float maxA = __uint_as_float(g_maxA_bits);
    const float invq = 16383.f / fmaxf(maxA, 1e-20f);
    const size_t i0 = ((size_t)blockIdx.x * 256 + threadIdx.x) * 4;
    const float4 v = *(const float4*)(g_x1f + i0);
    char4 d1, d2;
    {
        float q = v.x * invq; int a1 = min(127, __float2int_rn(q * 0.0078125f));
        d1.x = (signed char)a1; d2.x = (signed char)__float2int_rn(q - 128.f * a1);
    }
    {
        float q = v.y * invq; int a1 = min(127, __float2int_rn(q * 0.0078125f));
        d1.y = (signed char)a1; d2.y = (signed char)__float2int_rn(q - 128.f * a1);
    }
    {
        float q = v.z * invq; int a1 = min(127, __float2int_rn(q * 0.0078125f));
        d1.z = (signed char)a1; d2.z = (signed char)__float2int_rn(q - 128.f * a1);
    }
    {
        float q = v.w * invq; int a1 = min(127, __float2int_rn(q * 0.0078125f));
        d1.w = (signed char)a1; d2.w = (signed char)__float2int_rn(q - 128.f * a1);
    }
    *(char4*)(g_xq1 + i0) = d1;
    *(char4*)(g_xq2 + i0) = d2;
}

// =====================================================================
// Kernel 1d: pc weight transpose + int8 two-digit quantize
// [20736][256] -> [256][20736] x 2 digits
// =====================================================================
__global__ void wtransq_kernel(const float* __restrict__ w)
{
    __shared__ float tile[32][33];
    const float maxB = __uint_as_float(g_maxB_bits);
    const float invq = 16383.f / fmaxf(maxB, 1e-20f);
    const int k0 = blockIdx.x * 32, n0 = blockIdx.y * 32;
    const int tx = threadIdx.x, ty = threadIdx.y;
#pragma unroll
    for (int r = 0; r < 4; r++)
        tile[ty + 8 * r][tx] = w[(size_t)(k0 + ty + 8 * r) * 256 + n0 + tx];
    __syncthreads();
#pragma unroll
    for (int r = 0; r < 4; r++) {
        const float q = tile[tx][ty + 8 * r] * invq;
        int b1 = max(-127, min(127, __float2int_rn(q * 0.0078125f)));
        int b2 = __float2int_rn(q - 128.f * b1);
        const size_t off = (size_t)(n0 + ty + 8 * r) * 20736 + k0 + tx;
        g_wq1[off] = (signed char)b1;
        g_wq2[off] = (signed char)b2;
    }
}

// =====================================================================
// Kernel 2: primary-caps conv — int8 two-digit mma.sync GEMM.
// M=9216 N=256 K=20736. BM=128 BN=128, K=64/stage, 324 stages, 3-stage pipe.
// Accums: C1 = A1*B1 ; C2 = A1*B2 + A2*B1.  u = sA*sB*(16384*C1 + 128*C2).
// Smem: 4 slabs (A1,A2,B1,B2) of 128 rows x 80B pitch (64B data) = 40KB/stage.
// Pitch 80B: banks {20r+c mod 32 | r0..7,c0..3} = {0..31} -> conflict-free LDS.
// =====================================================================
#define PC_STAGE 40960
#define PC_NSTAGE 3

#define PC_ISSUE(s_) do {                                                   \
    const int k_ = (s_) * 64;                                               \
    const int ky_ = k_ / 2304;                                              \
    const int dA_ = ky_ * 5120 + (k_ - ky_ * 2304);                         \
    const uint32_t stg_ = sb + ((s_) % PC_NSTAGE) * PC_STAGE;               \
    const signed char* as_ = aPtr + dA_;                                    \
    const signed char* bs_ = bPtr + k_;                                     \
    cp16(stg_ + dstA + 0,  as_ + 0);  cp16(stg_ + dstA + 16, as_ + 16);     \
    cp16(stg_ + dstA + 32, as_ + 32); cp16(stg_ + dstA + 48, as_ + 48);     \
    cp16(stg_ + dstB + 0,  bs_ + 0);  cp16(stg_ + dstB + 16, bs_ + 16);     \
    cp16(stg_ + dstB + 32, bs_ + 32); cp16(stg_ + dstB + 48, bs_ + 48);     \
} while (0)

extern __shared__ __align__(128) unsigned char pc_smem[];

__global__ __launch_bounds__(256, 1) void pc_kernel(const float* __restrict__ bias)
{
    const uint32_t sb = smem_u32(pc_smem);
    const int tid = threadIdx.x;
    const int wid = tid >> 5;
    const int lane = tid & 31;
    const int mblock = blockIdx.x * 128;
    const int nbase = blockIdx.y * 128;
    const int warp_m = (wid >> 1) * 32;
    const int warp_n = (wid & 1) * 64;

    // ---- loader mapping: thread owns row r1 of (A-digit, B-digit) pair `grp` ----
    const int grp = tid >> 7;          // 0: A1/B1, 1: A2/B2
    const int r1 = tid & 127;
    const int m = mblock + r1;
    const int bimg = m / 36, p = m % 36;
    const int aBase = bimg * 102400 + (p / 6) * 10240 + (p % 6) * 512;
    const signed char* aPtr = (grp ? g_xq2 : g_xq1) + aBase;
    const signed char* bPtr = (grp ? g_wq2 : g_wq1) + (size_t)(nbase + r1) * 20736;
    const uint32_t dstA = (uint32_t)(grp * 10240 + r1 * 80);
    const uint32_t dstB = (uint32_t)(20480 + grp * 10240 + r1 * 80);

    // ---- fragment read offsets (byte offsets within a stage) ----
    const int gID = lane >> 2, tid4 = lane & 3;
    const uint32_t aRow = (uint32_t)((warp_m + gID) * 80 + tid4 * 4);
    const uint32_t bRow = (uint32_t)(20480 + (warp_n + gID) * 80 + tid4 * 4);

    int C1[2][8][4], C2[2][8][4];
#pragma unroll
    for (int mt = 0; mt < 2; mt++)
#pragma unroll
        for (int nt = 0; nt < 8; nt++)
#pragma unroll
            for (int q = 0; q < 4; q++) { C1[mt][nt][q] = 0; C2[mt][nt][q] = 0; }

    PC_ISSUE(0);
    asm volatile("cp.async.commit_group;" ::: "memory");
    PC_ISSUE(1);
    asm volatile("cp.async.commit_group;" ::: "memory");

    for (int s = 0; s < 324; s++) {
        if (s + 2 < 324) PC_ISSUE(s + 2);
        asm volatile("cp.async.commit_group;" ::: "memory");
        asm volatile("cp.async.wait_group 2;" ::: "memory");
        __syncthreads();

        const unsigned char* st = pc_smem + (uint32_t)(s % PC_NSTAGE) * PC_STAGE;

#pragma unroll
        for (int kk = 0; kk < 2; kk++) {
            int a1f[2][4], a2f[2][4];
#pragma unroll
            for (int mt = 0; mt < 2; mt++) {
                const uint32_t ab = aRow + mt * 1280 + kk * 32;
#pragma unroll
                for (int j = 0; j < 4; j++) {
                    const uint32_t o = ab + (j & 1) * 640 + (j >> 1) * 16;
                    a1f[mt][j] = *(const int*)(st + o);
                    a2f[mt][j] = *(const int*)(st + 10240 + o);
                }
            }
#pragma unroll
            for (int nt = 0; nt < 8; nt++) {
                const uint32_t bb = bRow + nt * 640 + kk * 32;
                const int b1r0 = *(const int*)(st + bb);
                const int b1r1 = *(const int*)(st + bb + 16);
                const int b2r0 = *(const int*)(st + 10240 + bb);
                const int b2r1 = *(const int*)(st + 10240 + bb + 16);
#pragma unroll
                for (int mt = 0; mt < 2; mt++) {
                    mma_s8(C1[mt][nt], a1f[mt], b1r0, b1r1);
                    mma_s8(C2[mt][nt], a1f[mt], b2r0, b2r1);
                    mma_s8(C2[mt][nt], a2f[mt], b1r0, b1r1);
                }
            }
        }
        __syncthreads();
    }

    // ---- epilogue: dequant + bias ----
    const float maxA = __uint_as_float(g_maxA_bits);
    const float maxB = __uint_as_float(g_maxB_bits);
    const float sc = (maxA / 16383.f) * (maxB / 16383.f);
    const float f1 = sc * 16384.f, f2 = sc * 128.f;
    const int tg = lane & 3;
#pragma unroll
    for (int nt = 0; nt < 8; nt++) {
        const int col = nbase + warp_n + nt * 8 + tg * 2;
        const float b0 = bias[col], b1 = bias[col + 1];
#pragma unroll
        for (int mt = 0; mt < 2; mt++) {
            const int row = mblock + warp_m + mt * 16 + gID;
            const int* c1 = C1[mt][nt];
            const int* c2 = C2[mt][nt];
            float2 o0 = make_float2(f1 * c1[0] + f2 * c2[0] + b0,
                                    f1 * c1[1] + f2 * c2[1] + b1);
            float2 o1 = make_float2(f1 * c1[2] + f2 * c2[2] + b0,
                                    f1 * c1[3] + f2 * c2[3] + b1);
            *(float2*)(g_u + (size_t)row * 256 + col) = o0;
            *(float2*)(g_u + (size_t)(row + 8) * 256 + col) = o1;
        }
    }
}

// =====================================================================
// Kernel 3: u_hat[b,i,jk] = sum_m W[i,jk,m]*u[b,i,m]  (fp32 out)
// =====================================================================
__global__ __launch_bounds__(320) void uhat_kernel(const float* __restrict__ wp)
{
    __shared__ float Ws[1280];
    const int i = blockIdx.x;
    const int tid = threadIdx.x;
    for (int t = tid; t < 1280; t += 320) Ws[t] = wp[(size_t)i * 1280 + t];
    __syncthreads();

    const int blane = tid / 40;
    const int jkg = tid - blane * 40;

    float w[32];
#pragma unroll
    for (int q = 0; q < 4; q++)
#pragma unroll
        for (int mm = 0; mm < 8; mm++) w[q * 8 + mm] = Ws[(jkg * 4 + q) * 8 + mm];

    const float* ubase = g_u + (size_t)i * 8;
    float* obase = g_uhat + (size_t)i * 160 + jkg * 4;

    for (int it = 0; it < 32; it++) {
        const int b = it * 8 + blane;
        const float4 u0 = *(const float4*)(ubase + (size_t)b * 9216);
        const float4 u1 = *(const float4*)(ubase + (size_t)b * 9216 + 4);
        float4 res;
        float* rp = (float*)&res;
#pragma unroll
        for (int q = 0; q < 4; q++) {
            const float* wq = w + q * 8;
            rp[q] = wq[0] * u0.x + wq[1] * u0.y + wq[2] * u0.z + wq[3] * u0.w +
                    wq[4] * u1.x + wq[5] * u1.y + wq[6] * u1.z + wq[7] * u1.w;
        }
        *(float4*)(obase + (size_t)b * 184320) = res;
    }
}

// =====================================================================
// Kernel 4: routing — 3 fused passes (b-linearity)
// =====================================================================
__device__ __forceinline__ void reduce_squash(
    const float acc[10], int tid, int g, int k,
    float red[16][160], float* sbuf, float* coef, float* vdst, float scale)
{
#pragma unroll
    for (int j = 0; j < 10; j++) red[g][j * 16 + k] = acc[j];
    __syncthreads();
    if (tid < 160) {
        float s = 0.f;
#pragma unroll
        for (int g2 = 0; g2 < 16; g2++) s += red[g2][tid];
        sbuf[tid] = s * scale;
    }
    __syncthreads();
    if (tid < 10) {
        float sn2 = 0.f;
#pragma unroll
        for (int kk = 0; kk < 16; kk++) { const float t = sbuf[tid * 16 + kk]; sn2 += t * t; }
        coef[tid] = sn2 / ((1.f + sn2) * (sqrtf(sn2) + EPSF));
    }
    __syncthreads();
    if (tid < 160) vdst[tid] = coef[tid >> 4] * sbuf[tid];
    __syncthreads();
}

__global__ __launch_bounds__(256) void routing_kernel(
    const float* __restrict__ y, float* __restrict__ vout)
{
    __shared__ float red[16][160];
    __shared__ float sbuf[160];
    __shared__ float coef[10];
    __shared__ float v0[160];
    __shared__ float vcur[160];

    const int b = blockIdx.x;
    const int tid = threadIdx.x;
    const int g = tid >> 4, k = tid & 15;
    const float* uh = g_uhat + (size_t)b * 184320;

    float acc[10];

#pragma unroll
    for (int j = 0; j < 10; j++) acc[j] = 0.f;
    for (int i = g; i < 1152; i += 16) {
        const float* r = uh + (size_t)i * 160 + k;
#pragma unroll
        for (int j = 0; j < 10; j++) acc[j] += r[j * 16];
    }
    reduce_squash(acc, tid, g, k, red, sbuf, coef, v0, 0.1f);
    if (tid < 160) vcur[tid] = v0[tid];
    __syncthreads();

    for (int pass = 0; pass < 2; pass++) {
        float vr[10];
#pragma unroll
        for (int j = 0; j < 10; j++) vr[j] = vcur[j * 16 + k];
#pragma unroll
        for (int j = 0; j < 10; j++) acc[j] = 0.f;

        for (int i = g; i < 1152; i += 16) {
            const float* r = uh + (size_t)i * 160 + k;
            float u[10], a[10];
#pragma unroll
            for (int j = 0; j < 10; j++) u[j] = r[j * 16];
#pragma unroll
            for (int j = 0; j < 10; j++) {
                float d = u[j] * vr[j];
                d += __shfl_xor_sync(0xffffffffu, d, 1);
                d += __shfl_xor_sync(0xffffffffu, d, 2);
                d += __shfl_xor_sync(0xffffffffu, d, 4);
                d += __shfl_xor_sync(0xffffffffu, d, 8);
                a[j] = d;
            }
            float mx = a[0];
#pragma unroll
            for (int j = 1; j < 10; j++) mx = fmaxf(mx, a[j]);
            float sum = 0.f;
#pragma unroll
            for (int j = 0; j < 10; j++) { a[j] = __expf(a[j] - mx); sum += a[j]; }
            const float inv = __fdividef(1.f, sum);
#pragma unroll
            for (int j = 0; j < 10; j++) acc[j] += a[j] * inv * u[j];
        }
        reduce_squash(acc, tid, g, k, red, sbuf, coef, vcur, 1.f);
        if (pass == 0) {
            if (tid < 160) vcur[tid] += v0[tid];
            __syncthreads();
        }
    }

    if (tid < 160) {
        const float v = vcur[tid];
        vout[(size_t)b * 160 + tid] = v;
        g_h0[(size_t)b * 160 + tid] = y[b * 10 + (tid >> 4)] * v;
    }
}

// =====================================================================
// Kernel 5-7: decoder GEMMs
// =====================================================================
template <int K, int N, int ACT>
__device__ __forceinline__ void gemm_body(
    const float* __restrict__ A, const float* __restrict__ W,
    const float* __restrict__ bias, float* __restrict__ C)
{
    __shared__ float As[16][68];
    __shared__ float Bs[16][68];
    const int tid = threadIdx.x;
    const int n0 = blockIdx.x * 64;
    const int m0 = blockIdx.y * 64;
    const int ty = tid >> 4, tx = tid & 15;
    const int ar = tid >> 2, ak = (tid & 3) * 4;
    const int bk = tid >> 4, bc = (tid & 15) * 4;

    float acc[4][4];
#pragma unroll
    for (int r = 0; r < 4; r++)
#pragma unroll
        for (int q = 0; q < 4; q++) acc[r][q] = 0.f;

    for (int k0 = 0; k0 < K; k0 += 16) {
        const float4 av = *(const float4*)(A + (size_t)(m0 + ar) * K + k0 + ak);
        float4 bv = make_float4(0.f, 0.f, 0.f, 0.f);
        if (n0 + bc < N) bv = *(const float4*)(W + (size_t)(k0 + bk) * N + n0 + bc);
        __syncthreads();
        As[ak + 0][ar] = av.x;
        As[ak + 1][ar] = av.y;
        As[ak + 2][ar] = av.z;
        As[ak + 3][ar] = av.w;
        *(float4*)&Bs[bk][bc] = bv;
        __syncthreads();
#pragma unroll
        for (int kk = 0; kk < 16; kk++) {
            const float4 a4 = *(const float4*)&As[kk][ty * 4];
            const float4 b4 = *(const float4*)&Bs[kk][tx * 4];
            const float aa[4] = {a4.x, a4.y, a4.z, a4.w};
            const float bb[4] = {b4.x, b4.y, b4.z, b4.w};
#pragma unroll
            for (int r = 0; r < 4; r++)
#pragma unroll
                for (int q = 0; q < 4; q++) acc[r][q] += aa[r] * bb[q];
        }
    }

    if (n0 + tx * 4 < N) {
        const float4 bv = *(const float4*)(bias + n0 + tx * 4);
        const float bb[4] = {bv.x, bv.y, bv.z, bv.w};
#pragma unroll
        for (int r = 0; r < 4; r++) {
            const int mm = m0 + ty * 4 + r;
            float o[4];
#pragma unroll
            for (int q = 0; q < 4; q++) {
                float v = acc[r][q] + bb[q];
                if (ACT == 0) v = fmaxf(v, 0.f);
                else          v = 1.f / (1.f + __expf(-v));
                o[q] = v;
            }
            *(float4*)(C + (size_t)mm * N + n0 + tx * 4) = make_float4(o[0], o[1], o[2], o[3]);
        }
    }
}

__global__ __launch_bounds__(256) void dec1_kernel(const float* __restrict__ W,
                                                   const float* __restrict__ b)
{ gemm_body<160, 512, 0>(g_h0, W, b, g_h1); }

__global__ __launch_bounds__(256) void dec2_kernel(const float* __restrict__ W,
                                                   const float* __restrict__ b)
{ gemm_body<512, 1024, 0>(g_h1, W, b, g_h2); }

__global__ __launch_bounds__(256) void dec3_kernel(const float* __restrict__ W,
                                                   const float* __restrict__ b,
                                                   float* __restrict__ out)
{ gemm_body<1024, 784, 1>(g_h2, W, b, out); }

// =====================================================================
extern "C" void kernel_launch(void* const* d_in, const int* in_sizes, int n_in,
                              void* d_out, int out_size)
{
    const float* input_x = (const float*)d_in[0];
    const float* y       = (const float*)d_in[1];
    const float* conv1_w = (const float*)d_in[2];
    const float* conv1_b = (const float*)d_in[3];
    const float* pc_w    = (const float*)d_in[4];
    const float* pc_b    = (const float*)d_in[5];
    const float* w_pose  = (const float*)d_in[6];
    const float* d1_w    = (const float*)d_in[7];
    const float* d1_b    = (const float*)d_in[8];
    const float* d2_w    = (const float*)d_in[9];
    const float* d2_b    = (const float*)d_in[10];
    const float* d3_w    = (const float*)d_in[11];
    const float* d3_b    = (const float*)d_in[12];
    float* out = (float*)d_out;

    cudaFuncSetAttribute(pc_kernel, cudaFuncAttributeMaxDynamicSharedMemorySize,
                         PC_NSTAGE * PC_STAGE);

    init_kernel<<<1, 1>>>();
    conv1_kernel<<<512, 256>>>(input_x, conv1_w, conv1_b);
    maxB_kernel<<<512, 256>>>(pc_w);
    quantA_kernel<<<25600, 256>>>();
    wtransq_kernel<<<dim3(648, 8), dim3(32, 8)>>>(pc_w);
    pc_kernel<<<dim3(72, 2), 256, PC_NSTAGE * PC_STAGE>>>(pc_b);
    uhat_kernel<<<1152, 320>>>(w_pose);
    routing_kernel<<<BATCH, 256>>>(y, out);
    dec1_kernel<<<dim3(8, 4), 256>>>(d1_w, d1_b);
    dec2_kernel<<<dim3(16, 4), 256>>>(d2_w, d2_b);
    dec3_kernel<<<dim3(13, 4), 256>>>(d3_w, d3_b, out + BATCH * 160);
    (void)in_sizes; (void)n_in; (void)out_size;
}

// round 10
// speedup vs baseline: 2.4426x; 1.0867x over previous
#include <cuda_runtime.h>
#include <cuda_bf16.h>
#include <cstdint>
#include <math.h>

#define EPSF 1e-7f
#define BATCH 256

// ---------------- scratch (device globals: no cudaMalloc allowed) ----------------
__device__ float g_x1f[BATCH * 400 * 256];            // conv1 out fp32  105 MB
__device__ signed char g_xq1[BATCH * 400 * 256];      // conv1 digit1 (int8)
__device__ signed char g_xq2[BATCH * 400 * 256];      // conv1 digit2
__device__ signed char g_wq1[256 * 20736];            // pc weights^T digit1
__device__ signed char g_wq2[256 * 20736];            // pc weights^T digit2
__device__ unsigned g_maxA_bits, g_maxB_bits;
__device__ float g_u[9216 * 256];                     // primary caps (fp32)
__device__ float g_uhat[BATCH * 1152 * 160];          // u_hat fp32   189 MB
__device__ float g_h0[BATCH * 160];
__device__ float g_h1[BATCH * 512];
__device__ float g_h2[BATCH * 1024];

// ======================= helpers (base-sm_100 features only) =======================
__device__ __forceinline__ uint32_t smem_u32(const void* p) {
    uint32_t a;
    asm("{ .reg .u64 t; cvta.to.shared.u64 t, %1; cvt.u32.u64 %0, t; }" : "=r"(a) : "l"(p));
    return a;
}
__device__ __forceinline__ void cp16(uint32_t dst, const void* src) {
    asm volatile("cp.async.cg.shared.global [%0], [%1], 16;" :: "r"(dst), "l"(src) : "memory");
}
__device__ __forceinline__ void ldsm4(int* r, uint32_t addr) {
    asm volatile("ldmatrix.sync.aligned.m8n8.x4.shared.b16 {%0,%1,%2,%3}, [%4];"
                 : "=r"(r[0]), "=r"(r[1]), "=r"(r[2]), "=r"(r[3]) : "r"(addr));
}
__device__ __forceinline__ void mma_s8(int* c, const int* a, int b0, int b1) {
    asm volatile(
        "mma.sync.aligned.m16n8k32.row.col.s32.s8.s8.s32 "
        "{%0,%1,%2,%3}, {%4,%5,%6,%7}, {%8,%9}, {%0,%1,%2,%3};"
        : "+r"(c[0]), "+r"(c[1]), "+r"(c[2]), "+r"(c[3])
        : "r"(a[0]), "r"(a[1]), "r"(a[2]), "r"(a[3]), "r"(b0), "r"(b1));
}

// =====================================================================
// Kernel 0: reset per-launch reductions
// =====================================================================
__global__ void init_kernel() { g_maxA_bits = 0u; g_maxB_bits = 0u; }

// =====================================================================
// Kernel 1: conv1 9x9 stride1 + ReLU -> fp32 + global max
// =====================================================================
__global__ __launch_bounds__(256) void conv1_kernel(
    const float* __restrict__ x, const float* __restrict__ w,
    const float* __restrict__ bias)
{
    __shared__ float img[784];
    const int b = blockIdx.x >> 1;
    const int half = blockIdx.x & 1;
    const int c = threadIdx.x;

    for (int t = threadIdx.x; t < 784; t += 256) img[t] = x[b * 784 + t];

    float wr[81];
#pragma unroll
    for (int k = 0; k < 81; k++) wr[k] = w[k * 256 + c];
    const float bv = bias[c];
    __syncthreads();

    float lmax = 0.f;
    const int oy0 = half * 10;
    for (int oy = oy0; oy < oy0 + 10; oy++) {
        for (int ox = 0; ox < 20; ox++) {
            float acc = bv;
            const float* ip = img + oy * 28 + ox;
#pragma unroll
            for (int ky = 0; ky < 9; ky++)
#pragma unroll
                for (int kx = 0; kx < 9; kx++)
                    acc += ip[ky * 28 + kx] * wr[ky * 9 + kx];
            const float v = fmaxf(acc, 0.f);
            lmax = fmaxf(lmax, v);
            g_x1f[((size_t)(b * 20 + oy) * 20 + ox) * 256 + c] = v;
        }
    }
    atomicMax(&g_maxA_bits, __float_as_uint(lmax));   // v >= 0: bit order == float order
}

// =====================================================================
// Kernel 1b: max |w| of pc weights
// =====================================================================
__global__ __launch_bounds__(256) void maxB_kernel(const float* __restrict__ w)
{
    float lmax = 0.f;
    for (size_t i = (size_t)blockIdx.x * blockDim.x + threadIdx.x; i < 5308416u;
         i += (size_t)gridDim.x * blockDim.x)
        lmax = fmaxf(lmax, fabsf(w[i]));
    atomicMax(&g_maxB_bits, __float_as_uint(lmax));
}

// =====================================================================
// Kernel 1c: quantize conv1 output -> two int8 digits (base 128)
// =====================================================================
__global__ __launch_bounds__(256) void quantA_kernel()
{
    const float maxA = __uint_as_float(g_maxA_bits);
    const float invq = 16383.f / fmaxf(maxA, 1e-20f);
    const size_t i0 = ((size_t)blockIdx.x * 256 + threadIdx.x) * 4;
    const float4 v = *(const float4*)(g_x1f + i0);
    char4 d1, d2;
    {
        float q = v.x * invq; int a1 = min(127, __float2int_rn(q * 0.0078125f));
        d1.x = (signed char)a1; d2.x = (signed char)__float2int_rn(q - 128.f * a1);
    }
    {
        float q = v.y * invq; int a1 = min(127, __float2int_rn(q * 0.0078125f));
        d1.y = (signed char)a1; d2.y = (signed char)__float2int_rn(q - 128.f * a1);
    }
    {
        float q = v.z * invq; int a1 = min(127, __float2int_rn(q * 0.0078125f));
        d1.z = (signed char)a1; d2.z = (signed char)__float2int_rn(q - 128.f * a1);
    }
    {
        float q = v.w * invq; int a1 = min(127, __float2int_rn(q * 0.0078125f));
        d1.w = (signed char)a1; d2.w = (signed char)__float2int_rn(q - 128.f * a1);
    }
    *(char4*)(g_xq1 + i0) = d1;
    *(char4*)(g_xq2 + i0) = d2;
}

// =====================================================================
// Kernel 1d: pc weight transpose + int8 two-digit quantize
// =====================================================================
__global__ void wtransq_kernel(const float* __restrict__ w)
{
    __shared__ float tile[32][33];
    const float maxB = __uint_as_float(g_maxB_bits);
    const float invq = 16383.f / fmaxf(maxB, 1e-20f);
    const int k0 = blockIdx.x * 32, n0 = blockIdx.y * 32;
    const int tx = threadIdx.x, ty = threadIdx.y;
#pragma unroll
    for (int r = 0; r < 4; r++)
        tile[ty + 8 * r][tx] = w[(size_t)(k0 + ty + 8 * r) * 256 + n0 + tx];
    __syncthreads();
#pragma unroll
    for (int r = 0; r < 4; r++) {
        const float q = tile[tx][ty + 8 * r] * invq;
        int b1 = max(-127, min(127, __float2int_rn(q * 0.0078125f)));
        int b2 = __float2int_rn(q - 128.f * b1);
        const size_t off = (size_t)(n0 + ty + 8 * r) * 20736 + k0 + tx;
        g_wq1[off] = (signed char)b1;
        g_wq2[off] = (signed char)b2;
    }
}

// =====================================================================
// Kernel 2: primary-caps conv — int8 two-digit mma.sync GEMM.
// M=9216 N=256 K=20736. BM=128 BN=128, K=64/stage, 324 stages.
// 4-stage cp.async ring (160KB), ONE __syncthreads per stage.
// Fragments via ldmatrix.x4 (m8n8.b16 distribution == s8 frag layout).
// C1 = A1*B1 ; C2 = A1*B2 + A2*B1.  u = sA*sB*(16384*C1 + 128*C2).
// Slabs per stage: [A1|A2|B1|B2], 128 rows x 80B pitch (64B data).
// =====================================================================
#define PC_STAGE 40960
#define PC_NSTAGE 4

#define PC_ISSUE(s_) do {                                                   \
    const int k_ = (s_) * 64;                                               \
    const int ky_ = k_ / 2304;                                              \
    const int dA_ = ky_ * 5120 + (k_ - ky_ * 2304);                         \
    const uint32_t stg_ = sb + ((s_) % PC_NSTAGE) * PC_STAGE;               \
    const signed char* as_ = aPtr + dA_;                                    \
    const signed char* bs_ = bPtr + k_;                                     \
    cp16(stg_ + dstA + 0,  as_ + 0);  cp16(stg_ + dstA + 16, as_ + 16);     \
    cp16(stg_ + dstA + 32, as_ + 32); cp16(stg_ + dstA + 48, as_ + 48);     \
    cp16(stg_ + dstB + 0,  bs_ + 0);  cp16(stg_ + dstB + 16, bs_ + 16);     \
    cp16(stg_ + dstB + 32, bs_ + 32); cp16(stg_ + dstB + 48, bs_ + 48);     \
} while (0)

extern __shared__ __align__(128) unsigned char pc_smem[];

__global__ __launch_bounds__(256, 1) void pc_kernel(const float* __restrict__ bias)
{
    const uint32_t sb = smem_u32(pc_smem);
    const int tid = threadIdx.x;
    const int wid = tid >> 5;
    const int lane = tid & 31;
    const int mblock = blockIdx.x * 128;
    const int nbase = blockIdx.y * 128;
    const int warp_m = (wid >> 1) * 32;
    const int warp_n = (wid & 1) * 64;

    // ---- loader mapping: thread owns row r1 of (A-digit, B-digit) pair `grp` ----
    const int grp = tid >> 7;          // 0: A1/B1, 1: A2/B2
    const int r1 = tid & 127;
    const int m = mblock + r1;
    const int bimg = m / 36, p = m % 36;
    const int aBase = bimg * 102400 + (p / 6) * 10240 + (p % 6) * 512;
    const signed char* aPtr = (grp ? g_xq2 : g_xq1) + aBase;
    const signed char* bPtr = (grp ? g_wq2 : g_wq1) + (size_t)(nbase + r1) * 20736;
    const uint32_t dstA = (uint32_t)(grp * 10240 + r1 * 80);
    const uint32_t dstB = (uint32_t)(20480 + grp * 10240 + r1 * 80);

    // ---- ldmatrix per-lane row addresses ----
    // A x4: mats {rows0-7 klo, rows8-15 klo, rows0-7 khi, rows8-15 khi}
    const int sel = lane >> 3, l7 = lane & 7;
    const uint32_t aL = (uint32_t)((warp_m + (sel & 1) * 8 + l7) * 80 + (sel >> 1) * 16);
    // B x4: mats {nt klo, nt khi, nt+1 klo, nt+1 khi}
    const uint32_t bL = (uint32_t)(20480 + (warp_n + (sel >> 1) * 8 + l7) * 80 + (sel & 1) * 16);

    int C1[2][8][4], C2[2][8][4];
#pragma unroll
    for (int mt = 0; mt < 2; mt++)
#pragma unroll
        for (int nt = 0; nt < 8; nt++)
#pragma unroll
            for (int q = 0; q < 4; q++) { C1[mt][nt][q] = 0; C2[mt][nt][q] = 0; }

    PC_ISSUE(0);
    asm volatile("cp.async.commit_group;" ::: "memory");
    PC_ISSUE(1);
    asm volatile("cp.async.commit_group;" ::: "memory");

    for (int s = 0; s < 324; s++) {
        if (s + 2 < 324) PC_ISSUE(s + 2);
        asm volatile("cp.async.commit_group;" ::: "memory");
        asm volatile("cp.async.wait_group 2;" ::: "memory");   // stage s resident
        __syncthreads();   // single barrier: 4-deep ring makes trailing sync unnecessary

        const uint32_t st = sb + (uint32_t)(s % PC_NSTAGE) * PC_STAGE;

#pragma unroll
        for (int kk = 0; kk < 2; kk++) {
            int a1f[2][4], a2f[2][4], b1f[4][4], b2f[4][4];
#pragma unroll
            for (int mt = 0; mt < 2; mt++) {
                ldsm4(a1f[mt], st + aL + mt * 1280 + kk * 32);
                ldsm4(a2f[mt], st + 10240 + aL + mt * 1280 + kk * 32);
            }
#pragma unroll
            for (int ntp = 0; ntp < 4; ntp++) {
                ldsm4(b1f[ntp], st + bL + ntp * 1280 + kk * 32);
                ldsm4(b2f[ntp], st + 10240 + bL + ntp * 1280 + kk * 32);
            }
#pragma unroll
            for (int nt = 0; nt < 8; nt++) {
                const int ntp = nt >> 1, ix = (nt & 1) * 2;
                const int b1r0 = b1f[ntp][ix], b1r1 = b1f[ntp][ix + 1];
                const int b2r0 = b2f[ntp][ix], b2r1 = b2f[ntp][ix + 1];
#pragma unroll
                for (int mt = 0; mt < 2; mt++) {
                    mma_s8(C1[mt][nt], a1f[mt], b1r0, b1r1);
                    mma_s8(C2[mt][nt], a1f[mt], b2r0, b2r1);
                    mma_s8(C2[mt][nt], a2f[mt], b1r0, b1r1);
                }
            }
        }
    }

    // ---- epilogue: dequant + bias ----
    const float maxA = __uint_as_float(g_maxA_bits);
    const float maxB = __uint_as_float(g_maxB_bits);
    const float sc = (maxA / 16383.f) * (maxB / 16383.f);
    const float f1 = sc * 16384.f, f2 = sc * 128.f;
    const int gID = lane >> 2, tg = lane & 3;
#pragma unroll
    for (int nt = 0; nt < 8; nt++) {
        const int col = nbase + warp_n + nt * 8 + tg * 2;
        const float b0 = bias[col], b1 = bias[col + 1];
#pragma unroll
        for (int mt = 0; mt < 2; mt++) {
            const int row = mblock + warp_m + mt * 16 + gID;
            const int* c1 = C1[mt][nt];
            const int* c2 = C2[mt][nt];
            float2 o0 = make_float2(f1 * c1[0] + f2 * c2[0] + b0,
                                    f1 * c1[1] + f2 * c2[1] + b1);
            float2 o1 = make_float2(f1 * c1[2] + f2 * c2[2] + b0,
                                    f1 * c1[3] + f2 * c2[3] + b1);
            *(float2*)(g_u + (size_t)row * 256 + col) = o0;
            *(float2*)(g_u + (size_t)(row + 8) * 256 + col) = o1;
        }
    }
}

// =====================================================================
// Kernel 3: u_hat[b,i,jk] = sum_m W[i,jk,m]*u[b,i,m]  (fp32 out)
// =====================================================================
__global__ __launch_bounds__(320) void uhat_kernel(const float* __restrict__ wp)
{
    __shared__ float Ws[1280];
    const int i = blockIdx.x;
    const int tid = threadIdx.x;
    for (int t = tid; t < 1280; t += 320) Ws[t] = wp[(size_t)i * 1280 + t];
    __syncthreads();

    const int blane = tid / 40;
    const int jkg = tid - blane * 40;

    float w[32];
#pragma unroll
    for (int q = 0; q < 4; q++)
#pragma unroll
        for (int mm = 0; mm < 8; mm++) w[q * 8 + mm] = Ws[(jkg * 4 + q) * 8 + mm];

    const float* ubase = g_u + (size_t)i * 8;
    float* obase = g_uhat + (size_t)i * 160 + jkg * 4;

    for (int it = 0; it < 32; it++) {
        const int b = it * 8 + blane;
        const float4 u0 = *(const float4*)(ubase + (size_t)b * 9216);
        const float4 u1 = *(const float4*)(ubase + (size_t)b * 9216 + 4);
        float4 res;
        float* rp = (float*)&res;
#pragma unroll
        for (int q = 0; q < 4; q++) {
            const float* wq = w + q * 8;
            rp[q] = wq[0] * u0.x + wq[1] * u0.y + wq[2] * u0.z + wq[3] * u0.w +
                    wq[4] * u1.x + wq[5] * u1.y + wq[6] * u1.z + wq[7] * u1.w;
        }
        *(float4*)(obase + (size_t)b * 184320) = res;
    }
}

// =====================================================================
// Kernel 4: routing — 3 fused passes (b-linearity)
// =====================================================================
__device__ __forceinline__ void reduce_squash(
    const float acc[10], int tid, int g, int k,
    float red[16][160], float* sbuf, float* coef, float* vdst, float scale)
{
#pragma unroll
    for (int j = 0; j < 10; j++) red[g][j * 16 + k] = acc[j];
    __syncthreads();
    if (tid < 160) {
        float s = 0.f;
#pragma unroll
        for (int g2 = 0; g2 < 16; g2++) s += red[g2][tid];
        sbuf[tid] = s * scale;
    }
    __syncthreads();
    if (tid < 10) {
        float sn2 = 0.f;
#pragma unroll
        for (int kk = 0; kk < 16; kk++) { const float t = sbuf[tid * 16 + kk]; sn2 += t * t; }
        coef[tid] = sn2 / ((1.f + sn2) * (sqrtf(sn2) + EPSF));
    }
    __syncthreads();
    if (tid < 160) vdst[tid] = coef[tid >> 4] * sbuf[tid];
    __syncthreads();
}

__global__ __launch_bounds__(256) void routing_kernel(
    const float* __restrict__ y, float* __restrict__ vout)
{
    __shared__ float red[16][160];
    __shared__ float sbuf[160];
    __shared__ float coef[10];
    __shared__ float v0[160];
    __shared__ float vcur[160];

    const int b = blockIdx.x;
    const int tid = threadIdx.x;
    const int g = tid >> 4, k = tid & 15;
    const float* uh = g_uhat + (size_t)b * 184320;

    float acc[10];

#pragma unroll
    for (int j = 0; j < 10; j++) acc[j] = 0.f;
    for (int i = g; i < 1152; i += 16) {
        const float* r = uh + (size_t)i * 160 + k;
#pragma unroll
        for (int j = 0; j < 10; j++) acc[j] += r[j * 16];
    }
    reduce_squash(acc, tid, g, k, red, sbuf, coef, v0, 0.1f);
    if (tid < 160) vcur[tid] = v0[tid];
    __syncthreads();

    for (int pass = 0; pass < 2; pass++) {
        float vr[10];
#pragma unroll
        for (int j = 0; j < 10; j++) vr[j] = vcur[j * 16 + k];
#pragma unroll
        for (int j = 0; j < 10; j++) acc[j] = 0.f;

        for (int i = g; i < 1152; i += 16) {
            const float* r = uh + (size_t)i * 160 + k;
            float u[10], a[10];
#pragma unroll
            for (int j = 0; j < 10; j++) u[j] = r[j * 16];
#pragma unroll
            for (int j = 0; j < 10; j++) {
                float d = u[j] * vr[j];
                d += __shfl_xor_sync(0xffffffffu, d, 1);
                d += __shfl_xor_sync(0xffffffffu, d, 2);
                d += __shfl_xor_sync(0xffffffffu, d, 4);
                d += __shfl_xor_sync(0xffffffffu, d, 8);
                a[j] = d;
            }
            float mx = a[0];
#pragma unroll
            for (int j = 1; j < 10; j++) mx = fmaxf(mx, a[j]);
            float sum = 0.f;
#pragma unroll
            for (int j = 0; j < 10; j++) { a[j] = __expf(a[j] - mx); sum += a[j]; }
            const float inv = __fdividef(1.f, sum);
#pragma unroll
            for (int j = 0; j < 10; j++) acc[j] += a[j] * inv * u[j];
        }
        reduce_squash(acc, tid, g, k, red, sbuf, coef, vcur, 1.f);
        if (pass == 0) {
            if (tid < 160) vcur[tid] += v0[tid];
            __syncthreads();
        }
    }

    if (tid < 160) {
        const float v = vcur[tid];
        vout[(size_t)b * 160 + tid] = v;
        g_h0[(size_t)b * 160 + tid] = y[b * 10 + (tid >> 4)] * v;
    }
}

// =====================================================================
// Kernel 5-7: decoder GEMMs
// =====================================================================
template <int K, int N, int ACT>
__device__ __forceinline__ void gemm_body(
    const float* __restrict__ A, const float* __restrict__ W,
    const float* __restrict__ bias, float* __restrict__ C)
{
    __shared__ float As[16][68];
    __shared__ float Bs[16][68];
    const int tid = threadIdx.x;
    const int n0 = blockIdx.x * 64;
    const int m0 = blockIdx.y * 64;
    const int ty = tid >> 4, tx = tid & 15;
    const int ar = tid >> 2, ak = (tid & 3) * 4;
    const int bk = tid >> 4, bc = (tid & 15) * 4;

    float acc[4][4];
#pragma unroll
    for (int r = 0; r < 4; r++)
#pragma unroll
        for (int q = 0; q < 4; q++) acc[r][q] = 0.f;

    for (int k0 = 0; k0 < K; k0 += 16) {
        const float4 av = *(const float4*)(A + (size_t)(m0 + ar) * K + k0 + ak);
        float4 bv = make_float4(0.f, 0.f, 0.f, 0.f);
        if (n0 + bc < N) bv = *(const float4*)(W + (size_t)(k0 + bk) * N + n0 + bc);
        __syncthreads();
        As[ak + 0][ar] = av.x;
        As[ak + 1][ar] = av.y;
        As[ak + 2][ar] = av.z;
        As[ak + 3][ar] = av.w;
        *(float4*)&Bs[bk][bc] = bv;
        __syncthreads();
#pragma unroll
        for (int kk = 0; kk < 16; kk++) {
            const float4 a4 = *(const float4*)&As[kk][ty * 4];
            const float4 b4 = *(const float4*)&Bs[kk][tx * 4];
            const float aa[4] = {a4.x, a4.y, a4.z, a4.w};
            const float bb[4] = {b4.x, b4.y, b4.z, b4.w};
#pragma unroll
            for (int r = 0; r < 4; r++)
#pragma unroll
                for (int q = 0; q < 4; q++) acc[r][q] += aa[r] * bb[q];
        }
    }

    if (n0 + tx * 4 < N) {
        const float4 bv = *(const float4*)(bias + n0 + tx * 4);
        const float bb[4] = {bv.x, bv.y, bv.z, bv.w};
#pragma unroll
        for (int r = 0; r < 4; r++) {
            const int mm = m0 + ty * 4 + r;
            float o[4];
#pragma unroll
            for (int q = 0; q < 4; q++) {
                float v = acc[r][q] + bb[q];
                if (ACT == 0) v = fmaxf(v, 0.f);
                else          v = 1.f / (1.f + __expf(-v));
                o[q] = v;
            }
            *(float4*)(C + (size_t)mm * N + n0 + tx * 4) = make_float4(o[0], o[1], o[2], o[3]);
        }
    }
}

__global__ __launch_bounds__(256) void dec1_kernel(const float* __restrict__ W,
                                                   const float* __restrict__ b)
{ gemm_body<160, 512, 0>(g_h0, W, b, g_h1); }

__global__ __launch_bounds__(256) void dec2_kernel(const float* __restrict__ W,
                                                   const float* __restrict__ b)
{ gemm_body<512, 1024, 0>(g_h1, W, b, g_h2); }

__global__ __launch_bounds__(256) void dec3_kernel(const float* __restrict__ W,
                                                   const float* __restrict__ b,
                                                   float* __restrict__ out)
{ gemm_body<1024, 784, 1>(g_h2, W, b, out); }

// =====================================================================
extern "C" void kernel_launch(void* const* d_in, const int* in_sizes, int n_in,
                              void* d_out, int out_size)
{
    const float* input_x = (const float*)d_in[0];
    const float* y       = (const float*)d_in[1];
    const float* conv1_w = (const float*)d_in[2];
    const float* conv1_b = (const float*)d_in[3];
    const float* pc_w    = (const float*)d_in[4];
    const float* pc_b    = (const float*)d_in[5];
    const float* w_pose  = (const float*)d_in[6];
    const float* d1_w    = (const float*)d_in[7];
    const float* d1_b    = (const float*)d_in[8];
    const float* d2_w    = (const float*)d_in[9];
    const float* d2_b    = (const float*)d_in[10];
    const float* d3_w    = (const float*)d_in[11];
    const float* d3_b    = (const float*)d_in[12];
    float* out = (float*)d_out;

    cudaFuncSetAttribute(pc_kernel, cudaFuncAttributeMaxDynamicSharedMemorySize,
                         PC_NSTAGE * PC_STAGE);

    init_kernel<<<1, 1>>>();
    conv1_kernel<<<512, 256>>>(input_x, conv1_w, conv1_b);
    maxB_kernel<<<512, 256>>>(pc_w);
    quantA_kernel<<<25600, 256>>>();
    wtransq_kernel<<<dim3(648, 8), dim3(32, 8)>>>(pc_w);
    pc_kernel<<<dim3(72, 2), 256, PC_NSTAGE * PC_STAGE>>>(pc_b);
    uhat_kernel<<<1152, 320>>>(w_pose);
    routing_kernel<<<BATCH, 256>>>(y, out);
    dec1_kernel<<<dim3(8, 4), 256>>>(d1_w, d1_b);
    dec2_kernel<<<dim3(16, 4), 256>>>(d2_w, d2_b);
    dec3_kernel<<<dim3(13, 4), 256>>>(d3_w, d3_b, out + BATCH * 160);
    (void)in_sizes; (void)n_in; (void)out_size;
}

// round 11
// speedup vs baseline: 2.6234x; 1.0740x over previous
#include <cuda_runtime.h>
#include <cuda_bf16.h>
#include <cuda_fp16.h>
#include <cstdint>
#include <math.h>

#define EPSF 1e-7f
#define BATCH 256

// ---------------- scratch (device globals: no cudaMalloc allowed) ----------------
__device__ float g_x1f[BATCH * 400 * 256];            // conv1 out fp32  105 MB
__device__ signed char g_xq1[BATCH * 400 * 256];      // conv1 digit1 (int8)
__device__ signed char g_xq2[BATCH * 400 * 256];      // conv1 digit2
__device__ signed char g_wq1[256 * 20736];            // pc weights^T digit1
__device__ signed char g_wq2[256 * 20736];            // pc weights^T digit2
__device__ unsigned g_maxA_bits, g_maxB_bits;
__device__ float g_u[9216 * 256];                     // primary caps (fp32)
__device__ __half g_uhath[BATCH * 1152 * 160];        // u_hat fp16    94 MB
__device__ float g_h0[BATCH * 160];
__device__ float g_h1[BATCH * 512];
__device__ float g_h2[BATCH * 1024];

// ======================= helpers (base-sm_100 features only) =======================
__device__ __forceinline__ uint32_t smem_u32(const void* p) {
    uint32_t a;
    asm("{ .reg .u64 t; cvta.to.shared.u64 t, %1; cvt.u32.u64 %0, t; }" : "=r"(a) : "l"(p));
    return a;
}
__device__ __forceinline__ void cp16(uint32_t dst, const void* src) {
    asm volatile("cp.async.cg.shared.global [%0], [%1], 16;" :: "r"(dst), "l"(src) : "memory");
}
__device__ __forceinline__ void ldsm4(int* r, uint32_t addr) {
    asm volatile("ldmatrix.sync.aligned.m8n8.x4.shared.b16 {%0,%1,%2,%3}, [%4];"
                 : "=r"(r[0]), "=r"(r[1]), "=r"(r[2]), "=r"(r[3]) : "r"(addr));
}
__device__ __forceinline__ void mma_s8(int* c, const int* a, int b0, int b1) {
    asm volatile(
        "mma.sync.aligned.m16n8k32.row.col.s32.s8.s8.s32 "
        "{%0,%1,%2,%3}, {%4,%5,%6,%7}, {%8,%9}, {%0,%1,%2,%3};"
        : "+r"(c[0]), "+r"(c[1]), "+r"(c[2]), "+r"(c[3])
        : "r"(a[0]), "r"(a[1]), "r"(a[2]), "r"(a[3]), "r"(b0), "r"(b1));
}

// =====================================================================
// Kernel 0: reset per-launch reductions
// =====================================================================
__global__ void init_kernel() { g_maxA_bits = 0u; g_maxB_bits = 0u; }

// =====================================================================
// Kernel 1: conv1 9x9 stride1 + ReLU -> fp32 + global max
// =====================================================================
__global__ __launch_bounds__(256) void conv1_kernel(
    const float* __restrict__ x, const float* __restrict__ w,
    const float* __restrict__ bias)
{
    __shared__ float img[784];
    const int b = blockIdx.x >> 1;
    const int half = blockIdx.x & 1;
    const int c = threadIdx.x;

    for (int t = threadIdx.x; t < 784; t += 256) img[t] = x[b * 784 + t];

    float wr[81];
#pragma unroll
    for (int k = 0; k < 81; k++) wr[k] = w[k * 256 + c];
    const float bv = bias[c];
    __syncthreads();

    float lmax = 0.f;
    const int oy0 = half * 10;
    for (int oy = oy0; oy < oy0 + 10; oy++) {
        for (int ox = 0; ox < 20; ox++) {
            float acc = bv;
            const float* ip = img + oy * 28 + ox;
#pragma unroll
            for (int ky = 0; ky < 9; ky++)
#pragma unroll
                for (int kx = 0; kx < 9; kx++)
                    acc += ip[ky * 28 + kx] * wr[ky * 9 + kx];
            const float v = fmaxf(acc, 0.f);
            lmax = fmaxf(lmax, v);
            g_x1f[((size_t)(b * 20 + oy) * 20 + ox) * 256 + c] = v;
        }
    }
    atomicMax(&g_maxA_bits, __float_as_uint(lmax));   // v >= 0: bit order == float order
}

// =====================================================================
// Kernel 1b: max |w| of pc weights
// =====================================================================
__global__ __launch_bounds__(256) void maxB_kernel(const float* __restrict__ w)
{
    float lmax = 0.f;
    for (size_t i = (size_t)blockIdx.x * blockDim.x + threadIdx.x; i < 5308416u;
         i += (size_t)gridDim.x * blockDim.x)
        lmax = fmaxf(lmax, fabsf(w[i]));
    atomicMax(&g_maxB_bits, __float_as_uint(lmax));
}

// =====================================================================
// Kernel 1c: quantize conv1 output -> two int8 digits (base 128)
// =====================================================================
__global__ __launch_bounds__(256) void quantA_kernel()
{
    const float maxA = __uint_as_float(g_maxA_bits);
    const float invq = 16383.f / fmaxf(maxA, 1e-20f);
    const size_t i0 = ((size_t)blockIdx.x * 256 + threadIdx.x) * 4;
    const float4 v = *(const float4*)(g_x1f + i0);
    char4 d1, d2;
    {
        float q = v.x * invq; int a1 = min(127, __float2int_rn(q * 0.0078125f));
        d1.x = (signed char)a1; d2.x = (signed char)__float2int_rn(q - 128.f * a1);
    }
    {
        float q = v.y * invq; int a1 = min(127, __float2int_rn(q * 0.0078125f));
        d1.y = (signed char)a1; d2.y = (signed char)__float2int_rn(q - 128.f * a1);
    }
    {
        float q = v.z * invq; int a1 = min(127, __float2int_rn(q * 0.0078125f));
        d1.z = (signed char)a1; d2.z = (signed char)__float2int_rn(q - 128.f * a1);
    }
    {
        float q = v.w * invq; int a1 = min(127, __float2int_rn(q * 0.0078125f));
        d1.w = (signed char)a1; d2.w = (signed char)__float2int_rn(q - 128.f * a1);
    }
    *(char4*)(g_xq1 + i0) = d1;
    *(char4*)(g_xq2 + i0) = d2;
}

// =====================================================================
// Kernel 1d: pc weight transpose + int8 two-digit quantize
// =====================================================================
__global__ void wtransq_kernel(const float* __restrict__ w)
{
    __shared__ float tile[32][33];
    const float maxB = __uint_as_float(g_maxB_bits);
    const float invq = 16383.f / fmaxf(maxB, 1e-20f);
    const int k0 = blockIdx.x * 32, n0 = blockIdx.y * 32;
    const int tx = threadIdx.x, ty = threadIdx.y;
#pragma unroll
    for (int r = 0; r < 4; r++)
        tile[ty + 8 * r][tx] = w[(size_t)(k0 + ty + 8 * r) * 256 + n0 + tx];
    __syncthreads();
#pragma unroll
    for (int r = 0; r < 4; r++) {
        const float q = tile[tx][ty + 8 * r] * invq;
        int b1 = max(-127, min(127, __float2int_rn(q * 0.0078125f)));
        int b2 = __float2int_rn(q - 128.f * b1);
        const size_t off = (size_t)(n0 + ty + 8 * r) * 20736 + k0 + tx;
        g_wq1[off] = (signed char)b1;
        g_wq2[off] = (signed char)b2;
    }
}

// =====================================================================
// Kernel 2: primary-caps conv — int8 two-digit mma.sync GEMM.
// M=9216 N=256 K=20736. BM=128 BN=128, K=64/stage, 324 stages.
// 4-stage cp.async ring (160KB), ONE __syncthreads per stage.
// Fragments via ldmatrix.x4. C1 = A1*B1 ; C2 = A1*B2 + A2*B1.
// u = sA*sB*(16384*C1 + 128*C2).
// =====================================================================
#define PC_STAGE 40960
#define PC_NSTAGE 4

#define PC_ISSUE(s_) do {                                                   \
    const int k_ = (s_) * 64;                                               \
    const int ky_ = k_ / 2304;                                              \
    const int dA_ = ky_ * 5120 + (k_ - ky_ * 2304);                         \
    const uint32_t stg_ = sb + ((s_) % PC_NSTAGE) * PC_STAGE;               \
    const signed char* as_ = aPtr + dA_;                                    \
    const signed char* bs_ = bPtr + k_;                                     \
    cp16(stg_ + dstA + 0,  as_ + 0);  cp16(stg_ + dstA + 16, as_ + 16);     \
    cp16(stg_ + dstA + 32, as_ + 32); cp16(stg_ + dstA + 48, as_ + 48);     \
    cp16(stg_ + dstB + 0,  bs_ + 0);  cp16(stg_ + dstB + 16, bs_ + 16);     \
    cp16(stg_ + dstB + 32, bs_ + 32); cp16(stg_ + dstB + 48, bs_ + 48);     \
} while (0)

extern __shared__ __align__(128) unsigned char pc_smem[];

__global__ __launch_bounds__(256, 1) void pc_kernel(const float* __restrict__ bias)
{
    const uint32_t sb = smem_u32(pc_smem);
    const int tid = threadIdx.x;
    const int wid = tid >> 5;
    const int lane = tid & 31;
    const int mblock = blockIdx.x * 128;
    const int nbase = blockIdx.y * 128;
    const int warp_m = (wid >> 1) * 32;
    const int warp_n = (wid & 1) * 64;

    const int grp = tid >> 7;
    const int r1 = tid & 127;
    const int m = mblock + r1;
    const int bimg = m / 36, p = m % 36;
    const int aBase = bimg * 102400 + (p / 6) * 10240 + (p % 6) * 512;
    const signed char* aPtr = (grp ? g_xq2 : g_xq1) + aBase;
    const signed char* bPtr = (grp ? g_wq2 : g_wq1) + (size_t)(nbase + r1) * 20736;
    const uint32_t dstA = (uint32_t)(grp * 10240 + r1 * 80);
    const uint32_t dstB = (uint32_t)(20480 + grp * 10240 + r1 * 80);

    const int sel = lane >> 3, l7 = lane & 7;
    const uint32_t aL = (uint32_t)((warp_m + (sel & 1) * 8 + l7) * 80 + (sel >> 1) * 16);
    const uint32_t bL = (uint32_t)(20480 + (warp_n + (sel >> 1) * 8 + l7) * 80 + (sel & 1) * 16);

    int C1[2][8][4], C2[2][8][4];
#pragma unroll
    for (int mt = 0; mt < 2; mt++)
#pragma unroll
        for (int nt = 0; nt < 8; nt++)
#pragma unroll
            for (int q = 0; q < 4; q++) { C1[mt][nt][q] = 0; C2[mt][nt][q] = 0; }

    PC_ISSUE(0);
    asm volatile("cp.async.commit_group;" ::: "memory");
    PC_ISSUE(1);
    asm volatile("cp.async.commit_group;" ::: "memory");

    for (int s = 0; s < 324; s++) {
        if (s + 2 < 324) PC_ISSUE(s + 2);
        asm volatile("cp.async.commit_group;" ::: "memory");
        asm volatile("cp.async.wait_group 2;" ::: "memory");
        __syncthreads();

        const uint32_t st = sb + (uint32_t)(s % PC_NSTAGE) * PC_STAGE;

#pragma unroll
        for (int kk = 0; kk < 2; kk++) {
            int a1f[2][4], a2f[2][4], b1f[4][4], b2f[4][4];
#pragma unroll
            for (int mt = 0; mt < 2; mt++) {
                ldsm4(a1f[mt], st + aL + mt * 1280 + kk * 32);
                ldsm4(a2f[mt], st + 10240 + aL + mt * 1280 + kk * 32);
            }
#pragma unroll
            for (int ntp = 0; ntp < 4; ntp++) {
                ldsm4(b1f[ntp], st + bL + ntp * 1280 + kk * 32);
                ldsm4(b2f[ntp], st + 10240 + bL + ntp * 1280 + kk * 32);
            }
#pragma unroll
            for (int nt = 0; nt < 8; nt++) {
                const int ntp = nt >> 1, ix = (nt & 1) * 2;
                const int b1r0 = b1f[ntp][ix], b1r1 = b1f[ntp][ix + 1];
                const int b2r0 = b2f[ntp][ix], b2r1 = b2f[ntp][ix + 1];
#pragma unroll
                for (int mt = 0; mt < 2; mt++) {
                    mma_s8(C1[mt][nt], a1f[mt], b1r0, b1r1);
                    mma_s8(C2[mt][nt], a1f[mt], b2r0, b2r1);
                    mma_s8(C2[mt][nt], a2f[mt], b1r0, b1r1);
                }
            }
        }
    }

    const float maxA = __uint_as_float(g_maxA_bits);
    const float maxB = __uint_as_float(g_maxB_bits);
    const float sc = (maxA / 16383.f) * (maxB / 16383.f);
    const float f1 = sc * 16384.f, f2 = sc * 128.f;
    const int gID = lane >> 2, tg = lane & 3;
#pragma unroll
    for (int nt = 0; nt < 8; nt++) {
        const int col = nbase + warp_n + nt * 8 + tg * 2;
        const float b0 = bias[col], b1 = bias[col + 1];
#pragma unroll
        for (int mt = 0; mt < 2; mt++) {
            const int row = mblock + warp_m + mt * 16 + gID;
            const int* c1 = C1[mt][nt];
            const int* c2 = C2[mt][nt];
            float2 o0 = make_float2(f1 * c1[0] + f2 * c2[0] + b0,
                                    f1 * c1[1] + f2 * c2[1] + b1);
            float2 o1 = make_float2(f1 * c1[2] + f2 * c2[2] + b0,
                                    f1 * c1[3] + f2 * c2[3] + b1);
            *(float2*)(g_u + (size_t)row * 256 + col) = o0;
            *(float2*)(g_u + (size_t)(row + 8) * 256 + col) = o1;
        }
    }
}

// =====================================================================
// Kernel 3: u_hat[b,i,jk] = sum_m W[i,jk,m]*u[b,i,m]  -> fp16
// =====================================================================
__global__ __launch_bounds__(320) void uhat_kernel(const float* __restrict__ wp)
{
    __shared__ float Ws[1280];
    const int i = blockIdx.x;
    const int tid = threadIdx.x;
    for (int t = tid; t < 1280; t += 320) Ws[t] = wp[(size_t)i * 1280 + t];
    __syncthreads();

    const int blane = tid / 40;
    const int jkg = tid - blane * 40;

    float w[32];
#pragma unroll
    for (int q = 0; q < 4; q++)
#pragma unroll
        for (int mm = 0; mm < 8; mm++) w[q * 8 + mm] = Ws[(jkg * 4 + q) * 8 + mm];

    const float* ubase = g_u + (size_t)i * 8;
    __half* obase = g_uhath + (size_t)i * 160 + jkg * 4;

    for (int it = 0; it < 32; it++) {
        const int b = it * 8 + blane;
        const float4 u0 = *(const float4*)(ubase + (size_t)b * 9216);
        const float4 u1 = *(const float4*)(ubase + (size_t)b * 9216 + 4);
        float rp[4];
#pragma unroll
        for (int q = 0; q < 4; q++) {
            const float* wq = w + q * 8;
            rp[q] = wq[0] * u0.x + wq[1] * u0.y + wq[2] * u0.z + wq[3] * u0.w +
                    wq[4] * u1.x + wq[5] * u1.y + wq[6] * u1.z + wq[7] * u1.w;
        }
        __half2 ha = __floats2half2_rn(rp[0], rp[1]);
        __half2 hb = __floats2half2_rn(rp[2], rp[3]);
        __half2* op = (__half2*)(obase + (size_t)b * 184320);
        op[0] = ha;
        op[1] = hb;
    }
}

// =====================================================================
// Kernel 4: routing — 3 fused passes; u_hat (fp16) read ONCE per iteration.
// 512 threads = 32 groups (i-strips) x 16 lanes (k) for 2x occupancy.
// =====================================================================
__device__ __forceinline__ void reduce_squash(
    const float acc[10], int tid, int g, int k,
    float red[32][160], float* sbuf, float* coef, float* vdst, float scale)
{
#pragma unroll
    for (int j = 0; j < 10; j++) red[g][j * 16 + k] = acc[j];
    __syncthreads();
    if (tid < 160) {
        float s = 0.f;
#pragma unroll
        for (int g2 = 0; g2 < 32; g2++) s += red[g2][tid];
        sbuf[tid] = s * scale;
    }
    __syncthreads();
    if (tid < 10) {
        float sn2 = 0.f;
#pragma unroll
        for (int kk = 0; kk < 16; kk++) { const float t = sbuf[tid * 16 + kk]; sn2 += t * t; }
        coef[tid] = sn2 / ((1.f + sn2) * (sqrtf(sn2) + EPSF));
    }
    __syncthreads();
    if (tid < 160) vdst[tid] = coef[tid >> 4] * sbuf[tid];
    __syncthreads();
}

__global__ __launch_bounds__(512, 2) void routing_kernel(
    const float* __restrict__ y, float* __restrict__ vout)
{
    __shared__ float red[32][160];
    __shared__ float sbuf[160];
    __shared__ float coef[10];
    __shared__ float v0[160];
    __shared__ float vcur[160];

    const int b = blockIdx.x;
    const int tid = threadIdx.x;
    const int g = tid >> 4, k = tid & 15;
    const __half* uh = g_uhath + (size_t)b * 184320;

    float acc[10];

#pragma unroll
    for (int j = 0; j < 10; j++) acc[j] = 0.f;
    for (int i = g; i < 1152; i += 32) {
        const __half* r = uh + (size_t)i * 160 + k;
#pragma unroll
        for (int j = 0; j < 10; j++) acc[j] += __half2float(r[j * 16]);
    }
    reduce_squash(acc, tid, g, k, red, sbuf, coef, v0, 0.1f);
    if (tid < 160) vcur[tid] = v0[tid];
    __syncthreads();

    for (int pass = 0; pass < 2; pass++) {
        float vr[10];
#pragma unroll
        for (int j = 0; j < 10; j++) vr[j] = vcur[j * 16 + k];
#pragma unroll
        for (int j = 0; j < 10; j++) acc[j] = 0.f;

        for (int i = g; i < 1152; i += 32) {
            const __half* r = uh + (size_t)i * 160 + k;
            float u[10], a[10];
#pragma unroll
            for (int j = 0; j < 10; j++) u[j] = __half2float(r[j * 16]);
#pragma unroll
            for (int j = 0; j < 10; j++) {
                float d = u[j] * vr[j];
                d += __shfl_xor_sync(0xffffffffu, d, 1);
                d += __shfl_xor_sync(0xffffffffu, d, 2);
                d += __shfl_xor_sync(0xffffffffu, d, 4);
                d += __shfl_xor_sync(0xffffffffu, d, 8);
                a[j] = d;
            }
            float mx = a[0];
#pragma unroll
            for (int j = 1; j < 10; j++) mx = fmaxf(mx, a[j]);
            float sum = 0.f;
#pragma unroll
            for (int j = 0; j < 10; j++) { a[j] = __expf(a[j] - mx); sum += a[j]; }
            const float inv = __fdividef(1.f, sum);
#pragma unroll
            for (int j = 0; j < 10; j++) acc[j] += a[j] * inv * u[j];
        }
        reduce_squash(acc, tid, g, k, red, sbuf, coef, vcur, 1.f);
        if (pass == 0) {
            if (tid < 160) vcur[tid] += v0[tid];
            __syncthreads();
        }
    }

    if (tid < 160) {
        const float v = vcur[tid];
        vout[(size_t)b * 160 + tid] = v;
        g_h0[(size_t)b * 160 + tid] = y[b * 10 + (tid >> 4)] * v;
    }
}

// =====================================================================
// Kernel 5-7: decoder GEMMs
// =====================================================================
template <int K, int N, int ACT>
__device__ __forceinline__ void gemm_body(
    const float* __restrict__ A, const float* __restrict__ W,
    const float* __restrict__ bias, float* __restrict__ C)
{
    __shared__ float As[16][68];
    __shared__ float Bs[16][68];
    const int tid = threadIdx.x;
    const int n0 = blockIdx.x * 64;
    const int m0 = blockIdx.y * 64;
    const int ty = tid >> 4, tx = tid & 15;
    const int ar = tid >> 2, ak = (tid & 3) * 4;
    const int bk = tid >> 4, bc = (tid & 15) * 4;

    float acc[4][4];
#pragma unroll
    for (int r = 0; r < 4; r++)
#pragma unroll
        for (int q = 0; q < 4; q++) acc[r][q] = 0.f;

    for (int k0 = 0; k0 < K; k0 += 16) {
        const float4 av = *(const float4*)(A + (size_t)(m0 + ar) * K + k0 + ak);
        float4 bv = make_float4(0.f, 0.f, 0.f, 0.f);
        if (n0 + bc < N) bv = *(const float4*)(W + (size_t)(k0 + bk) * N + n0 + bc);
        __syncthreads();
        As[ak + 0][ar] = av.x;
        As[ak + 1][ar] = av.y;
        As[ak + 2][ar] = av.z;
        As[ak + 3][ar] = av.w;
        *(float4*)&Bs[bk][bc] = bv;
        __syncthreads();
#pragma unroll
        for (int kk = 0; kk < 16; kk++) {
            const float4 a4 = *(const float4*)&As[kk][ty * 4];
            const float4 b4 = *(const float4*)&Bs[kk][tx * 4];
            const float aa[4] = {a4.x, a4.y, a4.z, a4.w};
            const float bb[4] = {b4.x, b4.y, b4.z, b4.w};
#pragma unroll
            for (int r = 0; r < 4; r++)
#pragma unroll
                for (int q = 0; q < 4; q++) acc[r][q] += aa[r] * bb[q];
        }
    }

    if (n0 + tx * 4 < N) {
        const float4 bv = *(const float4*)(bias + n0 + tx * 4);
        const float bb[4] = {bv.x, bv.y, bv.z, bv.w};
#pragma unroll
        for (int r = 0; r < 4; r++) {
            const int mm = m0 + ty * 4 + r;
            float o[4];
#pragma unroll
            for (int q = 0; q < 4; q++) {
                float v = acc[r][q] + bb[q];
                if (ACT == 0) v = fmaxf(v, 0.f);
                else          v = 1.f / (1.f + __expf(-v));
                o[q] = v;
            }
            *(float4*)(C + (size_t)mm * N + n0 + tx * 4) = make_float4(o[0], o[1], o[2], o[3]);
        }
    }
}

__global__ __launch_bounds__(256) void dec1_kernel(const float* __restrict__ W,
                                                   const float* __restrict__ b)
{ gemm_body<160, 512, 0>(g_h0, W, b, g_h1); }

__global__ __launch_bounds__(256) void dec2_kernel(const float* __restrict__ W,
                                                   const float* __restrict__ b)
{ gemm_body<512, 1024, 0>(g_h1, W, b, g_h2); }

__global__ __launch_bounds__(256) void dec3_kernel(const float* __restrict__ W,
                                                   const float* __restrict__ b,
                                                   float* __restrict__ out)
{ gemm_body<1024, 784, 1>(g_h2, W, b, out); }

// =====================================================================
extern "C" void kernel_launch(void* const* d_in, const int* in_sizes, int n_in,
                              void* d_out, int out_size)
{
    const float* input_x = (const float*)d_in[0];
    const float* y       = (const float*)d_in[1];
    const float* conv1_w = (const float*)d_in[2];
    const float* conv1_b = (const float*)d_in[3];
    const float* pc_w    = (const float*)d_in[4];
    const float* pc_b    = (const float*)d_in[5];
    const float* w_pose  = (const float*)d_in[6];
    const float* d1_w    = (const float*)d_in[7];
    const float* d1_b    = (const float*)d_in[8];
    const float* d2_w    = (const float*)d_in[9];
    const float* d2_b    = (const float*)d_in[10];
    const float* d3_w    = (const float*)d_in[11];
    const float* d3_b    = (const float*)d_in[12];
    float* out = (float*)d_out;

    cudaFuncSetAttribute(pc_kernel, cudaFuncAttributeMaxDynamicSharedMemorySize,
                         PC_NSTAGE * PC_STAGE);

    init_kernel<<<1, 1>>>();
    conv1_kernel<<<512, 256>>>(input_x, conv1_w, conv1_b);
    maxB_kernel<<<512, 256>>>(pc_w);
    quantA_kernel<<<25600, 256>>>();
    wtransq_kernel<<<dim3(648, 8), dim3(32, 8)>>>(pc_w);
    pc_kernel<<<dim3(72, 2), 256, PC_NSTAGE * PC_STAGE>>>(pc_b);
    uhat_kernel<<<1152, 320>>>(w_pose);
    routing_kernel<<<BATCH, 512>>>(y, out);
    dec1_kernel<<<dim3(8, 4), 256>>>(d1_w, d1_b);
    dec2_kernel<<<dim3(16, 4), 256>>>(d2_w, d2_b);
    dec3_kernel<<<dim3(13, 4), 256>>>(d3_w, d3_b, out + BATCH * 160);
    (void)in_sizes; (void)n_in; (void)out_size;
}

// round 12
// speedup vs baseline: 3.0496x; 1.1624x over previous
#include <cuda_runtime.h>
#include <cuda_bf16.h>
#include <cuda_fp16.h>
#include <cstdint>
#include <math.h>

#define EPSF 1e-7f
#define BATCH 256

// ---------------- scratch (device globals: no cudaMalloc allowed) ----------------
__device__ float g_x1f[BATCH * 400 * 256];            // conv1 out fp32  105 MB
__device__ signed char g_xq1[BATCH * 400 * 256];      // conv1 digit1 (int8)
__device__ signed char g_xq2[BATCH * 400 * 256];      // conv1 digit2
__device__ signed char g_wq1[256 * 20736];            // pc weights^T digit1
__device__ signed char g_wq2[256 * 20736];            // pc weights^T digit2
__device__ unsigned g_maxA_bits, g_maxB_bits;
__device__ float g_u[9216 * 256];                     // primary caps (fp32)
__device__ __half g_uhath[BATCH * 1152 * 160];        // u_hat fp16    94 MB
__device__ float g_h0[BATCH * 160];
__device__ float g_h1[BATCH * 512];
__device__ float g_h2[BATCH * 1024];

// ======================= helpers (base-sm_100 features only) =======================
__device__ __forceinline__ uint32_t smem_u32(const void* p) {
    uint32_t a;
    asm("{ .reg .u64 t; cvta.to.shared.u64 t, %1; cvt.u32.u64 %0, t; }" : "=r"(a) : "l"(p));
    return a;
}
__device__ __forceinline__ void cp16(uint32_t dst, const void* src) {
    asm volatile("cp.async.cg.shared.global [%0], [%1], 16;" :: "r"(dst), "l"(src) : "memory");
}
__device__ __forceinline__ void ldsm4(int* r, uint32_t addr) {
    asm volatile("ldmatrix.sync.aligned.m8n8.x4.shared.b16 {%0,%1,%2,%3}, [%4];"
                 : "=r"(r[0]), "=r"(r[1]), "=r"(r[2]), "=r"(r[3]) : "r"(addr));
}
__device__ __forceinline__ void mma_s8(int* c, const int* a, int b0, int b1) {
    asm volatile(
        "mma.sync.aligned.m16n8k32.row.col.s32.s8.s8.s32 "
        "{%0,%1,%2,%3}, {%4,%5,%6,%7}, {%8,%9}, {%0,%1,%2,%3};"
        : "+r"(c[0]), "+r"(c[1]), "+r"(c[2]), "+r"(c[3])
        : "r"(a[0]), "r"(a[1]), "r"(a[2]), "r"(a[3]), "r"(b0), "r"(b1));
}
// packed f32x2 (compiles for base sm_100 — verified in round 3)
__device__ __forceinline__ unsigned long long pack2(float x) {
    unsigned long long r;
    asm("mov.b64 %0, {%1, %1};" : "=l"(r) : "f"(x));
    return r;
}
__device__ __forceinline__ unsigned long long fma2(unsigned long long a,
                                                   unsigned long long b,
                                                   unsigned long long c) {
    unsigned long long d;
    asm("fma.rn.f32x2 %0, %1, %2, %3;" : "=l"(d) : "l"(a), "l"(b), "l"(c));
    return d;
}
__device__ __forceinline__ float2 unpk2(unsigned long long v) {
    float2 r;
    asm("mov.b64 {%0, %1}, %2;" : "=f"(r.x), "=f"(r.y) : "l"(v));
    return r;
}

// =====================================================================
// Kernel 0: reset per-launch reductions
// =====================================================================
__global__ void init_kernel() { g_maxA_bits = 0u; g_maxB_bits = 0u; }

// =====================================================================
// Kernel 1: conv1 9x9 s1 + ReLU -> fp32 + global max.
// f32x2 pixel-pairing: acc2 = (out[ox], out[ox+1]); weight operand packed
// once into regs; img operand is a natural float2. A 4B-shifted shadow
// copy of the image makes every load an aligned LDS.64 (kx parity static).
// =====================================================================
__global__ __launch_bounds__(256) void conv1_kernel(
    const float* __restrict__ x, const float* __restrict__ w,
    const float* __restrict__ bias)
{
    __shared__ __align__(16) float img[784];
    __shared__ __align__(16) float imgs[784];   // imgs[t] = img[t+1]
    const int b = blockIdx.x >> 1;
    const int half = blockIdx.x & 1;
    const int c = threadIdx.x;

    for (int t = threadIdx.x; t < 784; t += 256) {
        const float v = x[b * 784 + t];
        img[t] = v;
        if (t > 0) imgs[t - 1] = v;
    }
    if (threadIdx.x == 0) imgs[783] = 0.f;

    unsigned long long wr2[81];
#pragma unroll
    for (int k = 0; k < 81; k++) wr2[k] = pack2(w[k * 256 + c]);
    const unsigned long long bias2 = pack2(bias[c]);
    __syncthreads();

    float lmax = 0.f;
    const int oy0 = half * 10;
    for (int oy = oy0; oy < oy0 + 10; oy++) {
        for (int oxp = 0; oxp < 10; oxp++) {
            const int base = oy * 28 + oxp * 2;       // even
            unsigned long long acc0 = bias2, acc1 = pack2(0.f);
#pragma unroll
            for (int ky = 0; ky < 9; ky++) {
                const int ro = base + ky * 28;        // even
#pragma unroll
                for (int kx = 0; kx < 9; kx++) {
                    unsigned long long iv;
                    if ((kx & 1) == 0)
                        iv = *(const unsigned long long*)(img + ro + kx);
                    else
                        iv = *(const unsigned long long*)(imgs + ro + kx - 1);
                    if (ky < 4) acc0 = fma2(wr2[ky * 9 + kx], iv, acc0);
                    else        acc1 = fma2(wr2[ky * 9 + kx], iv, acc1);
                }
            }
            const float2 a0 = unpk2(acc0);
            const float2 a1 = unpk2(acc1);
            const float v0 = fmaxf(a0.x + a1.x, 0.f);
            const float v1 = fmaxf(a0.y + a1.y, 0.f);
            lmax = fmaxf(lmax, fmaxf(v0, v1));
            const size_t pix = (size_t)(b * 20 + oy) * 20 + oxp * 2;
            g_x1f[pix * 256 + c] = v0;
            g_x1f[(pix + 1) * 256 + c] = v1;
        }
    }
    atomicMax(&g_maxA_bits, __float_as_uint(lmax));   // v >= 0: bit order == float order
}

// =====================================================================
// Kernel 1b: max |w| of pc weights
// =====================================================================
__global__ __launch_bounds__(256) void maxB_kernel(const float* __restrict__ w)
{
    float lmax = 0.f;
    for (size_t i = (size_t)blockIdx.x * blockDim.x + threadIdx.x; i < 5308416u;
         i += (size_t)gridDim.x * blockDim.x)
        lmax = fmaxf(lmax, fabsf(w[i]));
    atomicMax(&g_maxB_bits, __float_as_uint(lmax));
}

// =====================================================================
// Kernel 1c: quantize conv1 output -> two int8 digits (base 128)
// =====================================================================
__global__ __launch_bounds__(256) void quantA_kernel()
{
    const float maxA = __uint_as_float(g_maxA_bits);
    const float invq = 16383.f / fmaxf(maxA, 1e-20f);
    const size_t i0 = ((size_t)blockIdx.x * 256 + threadIdx.x) * 4;
    const float4 v = *(const float4*)(g_x1f + i0);
    char4 d1, d2;
    {
        float q = v.x * invq; int a1 = min(127, __float2int_rn(q * 0.0078125f));
        d1.x = (signed char)a1; d2.x = (signed char)__float2int_rn(q - 128.f * a1);
    }
    {
        float q = v.y * invq; int a1 = min(127, __float2int_rn(q * 0.0078125f));
        d1.y = (signed char)a1; d2.y = (signed char)__float2int_rn(q - 128.f * a1);
    }
    {
        float q = v.z * invq; int a1 = min(127, __float2int_rn(q * 0.0078125f));
        d1.z = (signed char)a1; d2.z = (signed char)__float2int_rn(q - 128.f * a1);
    }
    {
        float q = v.w * invq; int a1 = min(127, __float2int_rn(q * 0.0078125f));
        d1.w = (signed char)a1; d2.w = (signed char)__float2int_rn(q - 128.f * a1);
    }
    *(char4*)(g_xq1 + i0) = d1;
    *(char4*)(g_xq2 + i0) = d2;
}

// =====================================================================
// Kernel 1d: pc weight transpose + int8 two-digit quantize
// =====================================================================
__global__ void wtransq_kernel(const float* __restrict__ w)
{
    __shared__ float tile[32][33];
    const float maxB = __uint_as_float(g_maxB_bits);
    const float invq = 16383.f / fmaxf(maxB, 1e-20f);
    const int k0 = blockIdx.x * 32, n0 = blockIdx.y * 32;
    const int tx = threadIdx.x, ty = threadIdx.y;
#pragma unroll
    for (int r = 0; r < 4; r++)
        tile[ty + 8 * r][tx] = w[(size_t)(k0 + ty + 8 * r) * 256 + n0 + tx];
    __syncthreads();
#pragma unroll
    for (int r = 0; r < 4; r++) {
        const float q = tile[tx][ty + 8 * r] * invq;
        int b1 = max(-127, min(127, __float2int_rn(q * 0.0078125f)));
        int b2 = __float2int_rn(q - 128.f * b1);
        const size_t off = (size_t)(n0 + ty + 8 * r) * 20736 + k0 + tx;
        g_wq1[off] = (signed char)b1;
        g_wq2[off] = (signed char)b2;
    }
}

// =====================================================================
// Kernel 2: primary-caps conv — int8 two-digit mma.sync GEMM.
// M=9216 N=256 K=20736. BM=128 BN=128, K=64/stage, 324 stages.
// 4-stage cp.async ring (160KB), ONE __syncthreads per stage.
// Fragments via ldmatrix.x4. C1 = A1*B1 ; C2 = A1*B2 + A2*B1.
// u = sA*sB*(16384*C1 + 128*C2).
// =====================================================================
#define PC_STAGE 40960
#define PC_NSTAGE 4

#define PC_ISSUE(s_) do {                                                   \
    const int k_ = (s_) * 64;                                               \
    const int ky_ = k_ / 2304;                                              \
    const int dA_ = ky_ * 5120 + (k_ - ky_ * 2304);                         \
    const uint32_t stg_ = sb + ((s_) % PC_NSTAGE) * PC_STAGE;               \
    const signed char* as_ = aPtr + dA_;                                    \
    const signed char* bs_ = bPtr + k_;                                     \
    cp16(stg_ + dstA + 0,  as_ + 0);  cp16(stg_ + dstA + 16, as_ + 16);     \
    cp16(stg_ + dstA + 32, as_ + 32); cp16(stg_ + dstA + 48, as_ + 48);     \
    cp16(stg_ + dstB + 0,  bs_ + 0);  cp16(stg_ + dstB + 16, bs_ + 16);     \
    cp16(stg_ + dstB + 32, bs_ + 32); cp16(stg_ + dstB + 48, bs_ + 48);     \
} while (0)

extern __shared__ __align__(128) unsigned char pc_smem[];

__global__ __launch_bounds__(256, 1) void pc_kernel(const float* __restrict__ bias)
{
    const uint32_t sb = smem_u32(pc_smem);
    const int tid = threadIdx.x;
    const int wid = tid >> 5;
    const int lane = tid & 31;
    const int mblock = blockIdx.x * 128;
    const int nbase = blockIdx.y * 128;
    const int warp_m = (wid >> 1) * 32;
    const int warp_n = (wid & 1) * 64;

    const int grp = tid >> 7;
    const int r1 = tid & 127;
    const int m = mblock + r1;
    const int bimg = m / 36, p = m % 36;
    const int aBase = bimg * 102400 + (p / 6) * 10240 + (p % 6) * 512;
    const signed char* aPtr = (grp ? g_xq2 : g_xq1) + aBase;
    const signed char* bPtr = (grp ? g_wq2 : g_wq1) + (size_t)(nbase + r1) * 20736;
    const uint32_t dstA = (uint32_t)(grp * 10240 + r1 * 80);
    const uint32_t dstB = (uint32_t)(20480 + grp * 10240 + r1 * 80);

    const int sel = lane >> 3, l7 = lane & 7;
    const uint32_t aL = (uint32_t)((warp_m + (sel & 1) * 8 + l7) * 80 + (sel >> 1) * 16);
    const uint32_t bL = (uint32_t)(20480 + (warp_n + (sel >> 1) * 8 + l7) * 80 + (sel & 1) * 16);

    int C1[2][8][4], C2[2][8][4];
#pragma unroll
    for (int mt = 0; mt < 2; mt++)
#pragma unroll
        for (int nt = 0; nt < 8; nt++)
#pragma unroll
            for (int q = 0; q < 4; q++) { C1[mt][nt][q] = 0; C2[mt][nt][q] = 0; }

    PC_ISSUE(0);
    asm volatile("cp.async.commit_group;" ::: "memory");
    PC_ISSUE(1);
    asm volatile("cp.async.commit_group;" ::: "memory");

    for (int s = 0; s < 324; s++) {
        if (s + 2 < 324) PC_ISSUE(s + 2);
        asm volatile("cp.async.commit_group;" ::: "memory");
        asm volatile("cp.async.wait_group 2;" ::: "memory");
        __syncthreads();

        const uint32_t st = sb + (uint32_t)(s % PC_NSTAGE) * PC_STAGE;

#pragma unroll
        for (int kk = 0; kk < 2; kk++) {
            int a1f[2][4], a2f[2][4], b1f[4][4], b2f[4][4];
#pragma unroll
            for (int mt = 0; mt < 2; mt++) {
                ldsm4(a1f[mt], st + aL + mt * 1280 + kk * 32);
                ldsm4(a2f[mt], st + 10240 + aL + mt * 1280 + kk * 32);
            }
#pragma unroll
            for (int ntp = 0; ntp < 4; ntp++) {
                ldsm4(b1f[ntp], st + bL + ntp * 1280 + kk * 32);
                ldsm4(b2f[ntp], st + 10240 + bL + ntp * 1280 + kk * 32);
            }
#pragma unroll
            for (int nt = 0; nt < 8; nt++) {
                const int ntp = nt >> 1, ix = (nt & 1) * 2;
                const int b1r0 = b1f[ntp][ix], b1r1 = b1f[ntp][ix + 1];
                const int b2r0 = b2f[ntp][ix], b2r1 = b2f[ntp][ix + 1];
#pragma unroll
                for (int mt = 0; mt < 2; mt++) {
                    mma_s8(C1[mt][nt], a1f[mt], b1r0, b1r1);
                    mma_s8(C2[mt][nt], a1f[mt], b2r0, b2r1);
                    mma_s8(C2[mt][nt], a2f[mt], b1r0, b1r1);
                }
            }
        }
    }

    const float maxA = __uint_as_float(g_maxA_bits);
    const float maxB = __uint_as_float(g_maxB_bits);
    const float sc = (maxA / 16383.f) * (maxB / 16383.f);
    const float f1 = sc * 16384.f, f2 = sc * 128.f;
    const int gID = lane >> 2, tg = lane & 3;
#pragma unroll
    for (int nt = 0; nt < 8; nt++) {
        const int col = nbase + warp_n + nt * 8 + tg * 2;
        const float b0 = bias[col], b1 = bias[col + 1];
#pragma unroll
        for (int mt = 0; mt < 2; mt++) {
            const int row = mblock + warp_m + mt * 16 + gID;
            const int* c1 = C1[mt][nt];
            const int* c2 = C2[mt][nt];
            float2 o0 = make_float2(f1 * c1[0] + f2 * c2[0] + b0,
                                    f1 * c1[1] + f2 * c2[1] + b1);
            float2 o1 = make_float2(f1 * c1[2] + f2 * c2[2] + b0,
                                    f1 * c1[3] + f2 * c2[3] + b1);
            *(float2*)(g_u + (size_t)row * 256 + col) = o0;
            *(float2*)(g_u + (size_t)(row + 8) * 256 + col) = o1;
        }
    }
}

// =====================================================================
// Kernel 3: u_hat[b,i,jk] = sum_m W[i,jk,m]*u[b,i,m]  -> fp16
// =====================================================================
__global__ __launch_bounds__(320) void uhat_kernel(const float* __restrict__ wp)
{
    __shared__ float Ws[1280];
    const int i = blockIdx.x;
    const int tid = threadIdx.x;
    for (int t = tid; t < 1280; t += 320) Ws[t] = wp[(size_t)i * 1280 + t];
    __syncthreads();

    const int blane = tid / 40;
    const int jkg = tid - blane * 40;

    float w[32];
#pragma unroll
    for (int q = 0; q < 4; q++)
#pragma unroll
        for (int mm = 0; mm < 8; mm++) w[q * 8 + mm] = Ws[(jkg * 4 + q) * 8 + mm];

    const float* ubase = g_u + (size_t)i * 8;
    __half* obase = g_uhath + (size_t)i * 160 + jkg * 4;

    for (int it = 0; it < 32; it++) {
        const int b = it * 8 + blane;
        const float4 u0 = *(const float4*)(ubase + (size_t)b * 9216);
        const float4 u1 = *(const float4*)(ubase + (size_t)b * 9216 + 4);
        float rp[4];
#pragma unroll
        for (int q = 0; q < 4; q++) {
            const float* wq = w + q * 8;
            rp[q] = wq[0] * u0.x + wq[1] * u0.y + wq[2] * u0.z + wq[3] * u0.w +
                    wq[4] * u1.x + wq[5] * u1.y + wq[6] * u1.z + wq[7] * u1.w;
        }
        __half2 ha = __floats2half2_rn(rp[0], rp[1]);
        __half2 hb = __floats2half2_rn(rp[2], rp[3]);
        __half2* op = (__half2*)(obase + (size_t)b * 184320);
        op[0] = ha;
        op[1] = hb;
    }
}

// =====================================================================
// Kernel 4: routing — 3 fused passes; u_hat (fp16) read ONCE per iteration.
// 512 threads = 32 groups (i-strips) x 16 lanes (k).
// =====================================================================
__device__ __forceinline__ void reduce_squash(
    const float acc[10], int tid, int g, int k,
    float red[32][160], float* sbuf, float* coef, float* vdst, float scale)
{
#pragma unroll
    for (int j = 0; j < 10; j++) red[g][j * 16 + k] = acc[j];
    __syncthreads();
    if (tid < 160) {
        float s = 0.f;
#pragma unroll
        for (int g2 = 0; g2 < 32; g2++) s += red[g2][tid];
        sbuf[tid] = s * scale;
    }
    __syncthreads();
    if (tid < 10) {
        float sn2 = 0.f;
#pragma unroll
        for (int kk = 0; kk < 16; kk++) { const float t = sbuf[tid * 16 + kk]; sn2 += t * t; }
        coef[tid] = sn2 / ((1.f + sn2) * (sqrtf(sn2) + EPSF));
    }
    __syncthreads();
    if (tid < 160) vdst[tid] = coef[tid >> 4] * sbuf[tid];
    __syncthreads();
}

__global__ __launch_bounds__(512, 2) void routing_kernel(
    const float* __restrict__ y, float* __restrict__ vout)
{
    __shared__ float red[32][160];
    __shared__ float sbuf[160];
    __shared__ float coef[10];
    __shared__ float v0[160];
    __shared__ float vcur[160];

    const int b = blockIdx.x;
    const int tid = threadIdx.x;
    const int g = tid >> 4, k = tid & 15;
    const __half* uh = g_uhath + (size_t)b * 184320;

    float acc[10];

#pragma unroll
    for (int j = 0; j < 10; j++) acc[j] = 0.f;
    for (int i = g; i < 1152; i += 32) {
        const __half* r = uh + (size_t)i * 160 + k;
#pragma unroll
        for (int j = 0; j < 10; j++) acc[j] += __half2float(r[j * 16]);
    }
    reduce_squash(acc, tid, g, k, red, sbuf, coef, v0, 0.1f);
    if (tid < 160) vcur[tid] = v0[tid];
    __syncthreads();

    for (int pass = 0; pass < 2; pass++) {
        float vr[10];
#pragma unroll
        for (int j = 0; j < 10; j++) vr[j] = vcur[j * 16 + k];
#pragma unroll
        for (int j = 0; j < 10; j++) acc[j] = 0.f;

        for (int i = g; i < 1152; i += 32) {
            const __half* r = uh + (size_t)i * 160 + k;
            float u[10], a[10];
#pragma unroll
            for (int j = 0; j < 10; j++) u[j] = __half2float(r[j * 16]);
#pragma unroll
            for (int j = 0; j < 10; j++) {
                float d = u[j] * vr[j];
                d += __shfl_xor_sync(0xffffffffu, d, 1);
                d += __shfl_xor_sync(0xffffffffu, d, 2);
                d += __shfl_xor_sync(0xffffffffu, d, 4);
                d += __shfl_xor_sync(0xffffffffu, d, 8);
                a[j] = d;
            }
            float mx = a[0];
#pragma unroll
            for (int j = 1; j < 10; j++) mx = fmaxf(mx, a[j]);
            float sum = 0.f;
#pragma unroll
            for (int j = 0; j < 10; j++) { a[j] = __expf(a[j] - mx); sum += a[j]; }
            const float inv = __fdividef(1.f, sum);
#pragma unroll
            for (int j = 0; j < 10; j++) acc[j] += a[j] * inv * u[j];
        }
        reduce_squash(acc, tid, g, k, red, sbuf, coef, vcur, 1.f);
        if (pass == 0) {
            if (tid < 160) vcur[tid] += v0[tid];
            __syncthreads();
        }
    }

    if (tid < 160) {
        const float v = vcur[tid];
        vout[(size_t)b * 160 + tid] = v;
        g_h0[(size_t)b * 160 + tid] = y[b * 10 + (tid >> 4)] * v;
    }
}

// =====================================================================
// Kernel 5-7: decoder GEMMs — BM=32, BN=64 (2x grid for occupancy)
// =====================================================================
template <int K, int N, int ACT>
__device__ __forceinline__ void gemm_body(
    const float* __restrict__ A, const float* __restrict__ W,
    const float* __restrict__ bias, float* __restrict__ C)
{
    __shared__ float As[16][36];
    __shared__ float Bs[16][68];
    const int tid = threadIdx.x;
    const int n0 = blockIdx.x * 64;
    const int m0 = blockIdx.y * 32;
    const int ty = tid >> 4, tx = tid & 15;       // rows ty*2, cols tx*4
    const int ar = tid >> 3, ak = (tid & 7) * 2;  // A: 32 rows x 8 float2
    const int bk = tid >> 4, bc = (tid & 15) * 4; // B: 16 rows x 16 float4

    float acc[2][4];
#pragma unroll
    for (int r = 0; r < 2; r++)
#pragma unroll
        for (int q = 0; q < 4; q++) acc[r][q] = 0.f;

    for (int k0 = 0; k0 < K; k0 += 16) {
        const float2 av = *(const float2*)(A + (size_t)(m0 + ar) * K + k0 + ak);
        float4 bv = make_float4(0.f, 0.f, 0.f, 0.f);
        if (n0 + bc < N) bv = *(const float4*)(W + (size_t)(k0 + bk) * N + n0 + bc);
        __syncthreads();
        As[ak][ar] = av.x;
        As[ak + 1][ar] = av.y;
        *(float4*)&Bs[bk][bc] = bv;
        __syncthreads();
#pragma unroll
        for (int kk = 0; kk < 16; kk++) {
            const float a0 = As[kk][ty * 2];
            const float a1 = As[kk][ty * 2 + 1];
            const float4 b4 = *(const float4*)&Bs[kk][tx * 4];
            const float bb[4] = {b4.x, b4.y, b4.z, b4.w};
#pragma unroll
            for (int q = 0; q < 4; q++) {
                acc[0][q] += a0 * bb[q];
                acc[1][q] += a1 * bb[q];
            }
        }
    }

    if (n0 + tx * 4 < N) {
        const float4 bv = *(const float4*)(bias + n0 + tx * 4);
        const float bb[4] = {bv.x, bv.y, bv.z, bv.w};
#pragma unroll
        for (int r = 0; r < 2; r++) {
            const int mm = m0 + ty * 2 + r;
            float o[4];
#pragma unroll
            for (int q = 0; q < 4; q++) {
                float v = acc[r][q] + bb[q];
                if (ACT == 0) v = fmaxf(v, 0.f);
                else          v = 1.f / (1.f + __expf(-v));
                o[q] = v;
            }
            *(float4*)(C + (size_t)mm * N + n0 + tx * 4) = make_float4(o[0], o[1], o[2], o[3]);
        }
    }
}

__global__ __launch_bounds__(256) void dec1_kernel(const float* __restrict__ W,
                                                   const float* __restrict__ b)
{ gemm_body<160, 512, 0>(g_h0, W, b, g_h1); }

__global__ __launch_bounds__(256) void dec2_kernel(const float* __restrict__ W,
                                                   const float* __restrict__ b)
{ gemm_body<512, 1024, 0>(g_h1, W, b, g_h2); }

__global__ __launch_bounds__(256) void dec3_kernel(const float* __restrict__ W,
                                                   const float* __restrict__ b,
                                                   float* __restrict__ out)
{ gemm_body<1024, 784, 1>(g_h2, W, b, out); }

// =====================================================================
extern "C" void kernel_launch(void* const* d_in, const int* in_sizes, int n_in,
                              void* d_out, int out_size)
{
    const float* input_x = (const float*)d_in[0];
    const float* y       = (const float*)d_in[1];
    const float* conv1_w = (const float*)d_in[2];
    const float* conv1_b = (const float*)d_in[3];
    const float* pc_w    = (const float*)d_in[4];
    const float* pc_b    = (const float*)d_in[5];
    const float* w_pose  = (const float*)d_in[6];
    const float* d1_w    = (const float*)d_in[7];
    const float* d1_b    = (const float*)d_in[8];
    const float* d2_w    = (const float*)d_in[9];
    const float* d2_b    = (const float*)d_in[10];
    const float* d3_w    = (const float*)d_in[11];
    const float* d3_b    = (const float*)d_in[12];
    float* out = (float*)d_out;

    cudaFuncSetAttribute(pc_kernel, cudaFuncAttributeMaxDynamicSharedMemorySize,
                         PC_NSTAGE * PC_STAGE);

    init_kernel<<<1, 1>>>();
    conv1_kernel<<<512, 256>>>(input_x, conv1_w, conv1_b);
    maxB_kernel<<<512, 256>>>(pc_w);
    quantA_kernel<<<25600, 256>>>();
    wtransq_kernel<<<dim3(648, 8), dim3(32, 8)>>>(pc_w);
    pc_kernel<<<dim3(72, 2), 256, PC_NSTAGE * PC_STAGE>>>(pc_b);
    uhat_kernel<<<1152, 320>>>(w_pose);
    routing_kernel<<<BATCH, 512>>>(y, out);
    dec1_kernel<<<dim3(8, 8), 256>>>(d1_w, d1_b);
    dec2_kernel<<<dim3(16, 8), 256>>>(d2_w, d2_b);
    dec3_kernel<<<dim3(13, 8), 256>>>(d3_w, d3_b, out + BATCH * 160);
    (void)in_sizes; (void)n_in; (void)out_size;
}

// round 13
// speedup vs baseline: 3.0909x; 1.0136x over previous
#include <cuda_runtime.h>
#include <cuda_bf16.h>
#include <cuda_fp16.h>
#include <cstdint>
#include <math.h>

#define EPSF 1e-7f
#define BATCH 256

// ---------------- scratch (device globals: no cudaMalloc allowed) ----------------
__device__ float g_x1f[BATCH * 400 * 256];            // conv1 out fp32  105 MB
__device__ signed char g_xq1[BATCH * 400 * 256];      // conv1 digit1 (int8)
__device__ signed char g_xq2[BATCH * 400 * 256];      // conv1 digit2
__device__ signed char g_wq1[256 * 20736];            // pc weights^T digit1
__device__ signed char g_wq2[256 * 20736];            // pc weights^T digit2
__device__ unsigned g_maxA_bits, g_maxB_bits;
__device__ float g_u[9216 * 256];                     // primary caps (fp32)
__device__ __half g_uhath[BATCH * 1152 * 160];        // u_hat fp16    94 MB
__device__ float g_h0[BATCH * 160];
__device__ float g_h1[BATCH * 512];
__device__ float g_h2[BATCH * 1024];

// ======================= helpers (base-sm_100 features only) =======================
__device__ __forceinline__ uint32_t smem_u32(const void* p) {
    uint32_t a;
    asm("{ .reg .u64 t; cvta.to.shared.u64 t, %1; cvt.u32.u64 %0, t; }" : "=r"(a) : "l"(p));
    return a;
}
__device__ __forceinline__ void cp16(uint32_t dst, const void* src) {
    asm volatile("cp.async.cg.shared.global [%0], [%1], 16;" :: "r"(dst), "l"(src) : "memory");
}
__device__ __forceinline__ void ldsm4(int* r, uint32_t addr) {
    asm volatile("ldmatrix.sync.aligned.m8n8.x4.shared.b16 {%0,%1,%2,%3}, [%4];"
                 : "=r"(r[0]), "=r"(r[1]), "=r"(r[2]), "=r"(r[3]) : "r"(addr));
}
__device__ __forceinline__ void mma_s8(int* c, const int* a, int b0, int b1) {
    asm volatile(
        "mma.sync.aligned.m16n8k32.row.col.s32.s8.s8.s32 "
        "{%0,%1,%2,%3}, {%4,%5,%6,%7}, {%8,%9}, {%0,%1,%2,%3};"
        : "+r"(c[0]), "+r"(c[1]), "+r"(c[2]), "+r"(c[3])
        : "r"(a[0]), "r"(a[1]), "r"(a[2]), "r"(a[3]), "r"(b0), "r"(b1));
}
// packed f32x2 (compiles for base sm_100 — verified in round 3)
__device__ __forceinline__ unsigned long long pack2(float x) {
    unsigned long long r;
    asm("mov.b64 %0, {%1, %1};" : "=l"(r) : "f"(x));
    return r;
}
__device__ __forceinline__ unsigned long long fma2(unsigned long long a,
                                                   unsigned long long b,
                                                   unsigned long long c) {
    unsigned long long d;
    asm("fma.rn.f32x2 %0, %1, %2, %3;" : "=l"(d) : "l"(a), "l"(b), "l"(c));
    return d;
}
__device__ __forceinline__ float2 unpk2(unsigned long long v) {
    float2 r;
    asm("mov.b64 {%0, %1}, %2;" : "=f"(r.x), "=f"(r.y) : "l"(v));
    return r;
}

// =====================================================================
// Kernel 0: reset per-launch reductions
// =====================================================================
__global__ void init_kernel() { g_maxA_bits = 0u; g_maxB_bits = 0u; }

// =====================================================================
// Kernel 1 (fused): blocks 0-511 conv1 9x9+ReLU (f32x2 pixel pairs) + maxA;
//                   blocks 512-639 maxB scan over pc weights.
// =====================================================================
__global__ __launch_bounds__(256) void conv1_maxB_kernel(
    const float* __restrict__ x, const float* __restrict__ w,
    const float* __restrict__ bias, const float* __restrict__ pcw)
{
    __shared__ __align__(16) float img[784];
    __shared__ __align__(16) float imgs[784];   // imgs[t] = img[t+1]

    if (blockIdx.x >= 512) {
        // ---- maxB part ----
        float lmax = 0.f;
        for (size_t i = (size_t)(blockIdx.x - 512) * 256 + threadIdx.x; i < 5308416u;
             i += 128u * 256u)
            lmax = fmaxf(lmax, fabsf(pcw[i]));
        atomicMax(&g_maxB_bits, __float_as_uint(lmax));
        return;
    }

    const int b = blockIdx.x >> 1;
    const int half = blockIdx.x & 1;
    const int c = threadIdx.x;

    for (int t = threadIdx.x; t < 784; t += 256) {
        const float v = x[b * 784 + t];
        img[t] = v;
        if (t > 0) imgs[t - 1] = v;
    }
    if (threadIdx.x == 0) imgs[783] = 0.f;

    unsigned long long wr2[81];
#pragma unroll
    for (int k = 0; k < 81; k++) wr2[k] = pack2(w[k * 256 + c]);
    const unsigned long long bias2 = pack2(bias[c]);
    __syncthreads();

    float lmax = 0.f;
    const int oy0 = half * 10;
    for (int oy = oy0; oy < oy0 + 10; oy++) {
        for (int oxp = 0; oxp < 10; oxp++) {
            const int base = oy * 28 + oxp * 2;       // even
            unsigned long long acc0 = bias2, acc1 = pack2(0.f);
#pragma unroll
            for (int ky = 0; ky < 9; ky++) {
                const int ro = base + ky * 28;        // even
#pragma unroll
                for (int kx = 0; kx < 9; kx++) {
                    unsigned long long iv;
                    if ((kx & 1) == 0)
                        iv = *(const unsigned long long*)(img + ro + kx);
                    else
                        iv = *(const unsigned long long*)(imgs + ro + kx - 1);
                    if (ky < 4) acc0 = fma2(wr2[ky * 9 + kx], iv, acc0);
                    else        acc1 = fma2(wr2[ky * 9 + kx], iv, acc1);
                }
            }
            const float2 a0 = unpk2(acc0);
            const float2 a1 = unpk2(acc1);
            const float v0 = fmaxf(a0.x + a1.x, 0.f);
            const float v1 = fmaxf(a0.y + a1.y, 0.f);
            lmax = fmaxf(lmax, fmaxf(v0, v1));
            const size_t pix = (size_t)(b * 20 + oy) * 20 + oxp * 2;
            g_x1f[pix * 256 + c] = v0;
            g_x1f[(pix + 1) * 256 + c] = v1;
        }
    }
    atomicMax(&g_maxA_bits, __float_as_uint(lmax));   // v >= 0: bit order == float order
}

// =====================================================================
// Kernel 1c (fused): blocks 0-25599 quantize conv1 output -> two int8 digits;
//                    blocks 25600+ transpose+quantize pc weights.
// =====================================================================
__global__ __launch_bounds__(256) void quant_kernel(const float* __restrict__ w)
{
    __shared__ float tile[32][33];
    const int tid = threadIdx.x;

    if (blockIdx.x < 25600) {
        const float maxA = __uint_as_float(g_maxA_bits);
        const float invq = 16383.f / fmaxf(maxA, 1e-20f);
        const size_t i0 = ((size_t)blockIdx.x * 256 + tid) * 4;
        const float4 v = *(const float4*)(g_x1f + i0);
        char4 d1, d2;
        {
            float q = v.x * invq; int a1 = min(127, __float2int_rn(q * 0.0078125f));
            d1.x = (signed char)a1; d2.x = (signed char)__float2int_rn(q - 128.f * a1);
        }
        {
            float q = v.y * invq; int a1 = min(127, __float2int_rn(q * 0.0078125f));
            d1.y = (signed char)a1; d2.y = (signed char)__float2int_rn(q - 128.f * a1);
        }
        {
            float q = v.z * invq; int a1 = min(127, __float2int_rn(q * 0.0078125f));
            d1.z = (signed char)a1; d2.z = (signed char)__float2int_rn(q - 128.f * a1);
        }
        {
            float q = v.w * invq; int a1 = min(127, __float2int_rn(q * 0.0078125f));
            d1.w = (signed char)a1; d2.w = (signed char)__float2int_rn(q - 128.f * a1);
        }
        *(char4*)(g_xq1 + i0) = d1;
        *(char4*)(g_xq2 + i0) = d2;
        return;
    }

    // ---- weight transpose + quantize: [20736][256] -> [256][20736] x2 digits ----
    const int q = blockIdx.x - 25600;            // 0 .. 5183
    const int k0 = (q % 648) * 32, n0 = (q / 648) * 32;
    const int tx = tid & 31, ty = tid >> 5;      // 32 x 8
    const float maxB = __uint_as_float(g_maxB_bits);
    const float invq = 16383.f / fmaxf(maxB, 1e-20f);
#pragma unroll
    for (int r = 0; r < 4; r++)
        tile[ty + 8 * r][tx] = w[(size_t)(k0 + ty + 8 * r) * 256 + n0 + tx];
    __syncthreads();
#pragma unroll
    for (int r = 0; r < 4; r++) {
        const float qv = tile[tx][ty + 8 * r] * invq;
        int b1 = max(-127, min(127, __float2int_rn(qv * 0.0078125f)));
        int b2 = __float2int_rn(qv - 128.f * b1);
        const size_t off = (size_t)(n0 + ty + 8 * r) * 20736 + k0 + tx;
        g_wq1[off] = (signed char)b1;
        g_wq2[off] = (signed char)b2;
    }
}

// =====================================================================
// Kernel 2: primary-caps conv — int8 two-digit mma.sync GEMM.
// M=9216 N=256 K=20736. BM=128 BN=128, K=64/stage, 324 stages.
// 4-stage cp.async ring (160KB), ONE __syncthreads per stage.
// Fragments via ldmatrix.x4. C1 = A1*B1 ; C2 = A1*B2 + A2*B1.
// u = sA*sB*(16384*C1 + 128*C2).
// =====================================================================
#define PC_STAGE 40960
#define PC_NSTAGE 4

#define PC_ISSUE(s_) do {                                                   \
    const int k_ = (s_) * 64;                                               \
    const int ky_ = k_ / 2304;                                              \
    const int dA_ = ky_ * 5120 + (k_ - ky_ * 2304);                         \
    const uint32_t stg_ = sb + ((s_) % PC_NSTAGE) * PC_STAGE;               \
    const signed char* as_ = aPtr + dA_;                                    \
    const signed char* bs_ = bPtr + k_;                                     \
    cp16(stg_ + dstA + 0,  as_ + 0);  cp16(stg_ + dstA + 16, as_ + 16);     \
    cp16(stg_ + dstA + 32, as_ + 32); cp16(stg_ + dstA + 48, as_ + 48);     \
    cp16(stg_ + dstB + 0,  bs_ + 0);  cp16(stg_ + dstB + 16, bs_ + 16);     \
    cp16(stg_ + dstB + 32, bs_ + 32); cp16(stg_ + dstB + 48, bs_ + 48);     \
} while (0)

extern __shared__ __align__(128) unsigned char pc_smem[];

__global__ __launch_bounds__(256, 1) void pc_kernel(const float* __restrict__ bias)
{
    const uint32_t sb = smem_u32(pc_smem);
    const int tid = threadIdx.x;
    const int wid = tid >> 5;
    const int lane = tid & 31;
    const int mblock = blockIdx.x * 128;
    const int nbase = blockIdx.y * 128;
    const int warp_m = (wid >> 1) * 32;
    const int warp_n = (wid & 1) * 64;

    const int grp = tid >> 7;
    const int r1 = tid & 127;
    const int m = mblock + r1;
    const int bimg = m / 36, p = m % 36;
    const int aBase = bimg * 102400 + (p / 6) * 10240 + (p % 6) * 512;
    const signed char* aPtr = (grp ? g_xq2 : g_xq1) + aBase;
    const signed char* bPtr = (grp ? g_wq2 : g_wq1) + (size_t)(nbase + r1) * 20736;
    const uint32_t dstA = (uint32_t)(grp * 10240 + r1 * 80);
    const uint32_t dstB = (uint32_t)(20480 + grp * 10240 + r1 * 80);

    const int sel = lane >> 3, l7 = lane & 7;
    const uint32_t aL = (uint32_t)((warp_m + (sel & 1) * 8 + l7) * 80 + (sel >> 1) * 16);
    const uint32_t bL = (uint32_t)(20480 + (warp_n + (sel >> 1) * 8 + l7) * 80 + (sel & 1) * 16);

    int C1[2][8][4], C2[2][8][4];
#pragma unroll
    for (int mt = 0; mt < 2; mt++)
#pragma unroll
        for (int nt = 0; nt < 8; nt++)
#pragma unroll
            for (int q = 0; q < 4; q++) { C1[mt][nt][q] = 0; C2[mt][nt][q] = 0; }

    PC_ISSUE(0);
    asm volatile("cp.async.commit_group;" ::: "memory");
    PC_ISSUE(1);
    asm volatile("cp.async.commit_group;" ::: "memory");

    for (int s = 0; s < 324; s++) {
        if (s + 2 < 324) PC_ISSUE(s + 2);
        asm volatile("cp.async.commit_group;" ::: "memory");
        asm volatile("cp.async.wait_group 2;" ::: "memory");
        __syncthreads();

        const uint32_t st = sb + (uint32_t)(s % PC_NSTAGE) * PC_STAGE;

#pragma unroll
        for (int kk = 0; kk < 2; kk++) {
            int a1f[2][4], a2f[2][4], b1f[4][4], b2f[4][4];
#pragma unroll
            for (int mt = 0; mt < 2; mt++) {
                ldsm4(a1f[mt], st + aL + mt * 1280 + kk * 32);
                ldsm4(a2f[mt], st + 10240 + aL + mt * 1280 + kk * 32);
            }
#pragma unroll
            for (int ntp = 0; ntp < 4; ntp++) {
                ldsm4(b1f[ntp], st + bL + ntp * 1280 + kk * 32);
                ldsm4(b2f[ntp], st + 10240 + bL + ntp * 1280 + kk * 32);
            }
#pragma unroll
            for (int nt = 0; nt < 8; nt++) {
                const int ntp = nt >> 1, ix = (nt & 1) * 2;
                const int b1r0 = b1f[ntp][ix], b1r1 = b1f[ntp][ix + 1];
                const int b2r0 = b2f[ntp][ix], b2r1 = b2f[ntp][ix + 1];
#pragma unroll
                for (int mt = 0; mt < 2; mt++) {
                    mma_s8(C1[mt][nt], a1f[mt], b1r0, b1r1);
                    mma_s8(C2[mt][nt], a1f[mt], b2r0, b2r1);
                    mma_s8(C2[mt][nt], a2f[mt], b1r0, b1r1);
                }
            }
        }
    }

    const float maxA = __uint_as_float(g_maxA_bits);
    const float maxB = __uint_as_float(g_maxB_bits);
    const float sc = (maxA / 16383.f) * (maxB / 16383.f);
    const float f1 = sc * 16384.f, f2 = sc * 128.f;
    const int gID = lane >> 2, tg = lane & 3;
#pragma unroll
    for (int nt = 0; nt < 8; nt++) {
        const int col = nbase + warp_n + nt * 8 + tg * 2;
        const float b0 = bias[col], b1 = bias[col + 1];
#pragma unroll
        for (int mt = 0; mt < 2; mt++) {
            const int row = mblock + warp_m + mt * 16 + gID;
            const int* c1 = C1[mt][nt];
            const int* c2 = C2[mt][nt];
            float2 o0 = make_float2(f1 * c1[0] + f2 * c2[0] + b0,
                                    f1 * c1[1] + f2 * c2[1] + b1);
            float2 o1 = make_float2(f1 * c1[2] + f2 * c2[2] + b0,
                                    f1 * c1[3] + f2 * c2[3] + b1);
            *(float2*)(g_u + (size_t)row * 256 + col) = o0;
            *(float2*)(g_u + (size_t)(row + 8) * 256 + col) = o1;
        }
    }
}

// =====================================================================
// Kernel 3: u_hat[b,i,jk] = sum_m W[i,jk,m]*u[b,i,m] -> fp16.
// 2-way b-ILP: each iteration issues loads for b and b+8 up front.
// =====================================================================
__global__ __launch_bounds__(320) void uhat_kernel(const float* __restrict__ wp)
{
    __shared__ float Ws[1280];
    const int i = blockIdx.x;
    const int tid = threadIdx.x;
    for (int t = tid; t < 1280; t += 320) Ws[t] = wp[(size_t)i * 1280 + t];
    __syncthreads();

    const int blane = tid / 40;
    const int jkg = tid - blane * 40;

    float w[32];
#pragma unroll
    for (int q = 0; q < 4; q++)
#pragma unroll
        for (int mm = 0; mm < 8; mm++) w[q * 8 + mm] = Ws[(jkg * 4 + q) * 8 + mm];

    const float* ubase = g_u + (size_t)i * 8;
    __half* obase = g_uhath + (size_t)i * 160 + jkg * 4;

    for (int it = 0; it < 16; it++) {
        const int bA = it * 16 + blane;
        const int bB = bA + 8;
        const float4 uA0 = *(const float4*)(ubase + (size_t)bA * 9216);
        const float4 uA1 = *(const float4*)(ubase + (size_t)bA * 9216 + 4);
        const float4 uB0 = *(const float4*)(ubase + (size_t)bB * 9216);
        const float4 uB1 = *(const float4*)(ubase + (size_t)bB * 9216 + 4);
        float rA[4], rB[4];
#pragma unroll
        for (int q = 0; q < 4; q++) {
            const float* wq = w + q * 8;
            rA[q] = wq[0] * uA0.x + wq[1] * uA0.y + wq[2] * uA0.z + wq[3] * uA0.w +
                    wq[4] * uA1.x + wq[5] * uA1.y + wq[6] * uA1.z + wq[7] * uA1.w;
            rB[q] = wq[0] * uB0.x + wq[1] * uB0.y + wq[2] * uB0.z + wq[3] * uB0.w +
                    wq[4] * uB1.x + wq[5] * uB1.y + wq[6] * uB1.z + wq[7] * uB1.w;
        }
        __half2* opA = (__half2*)(obase + (size_t)bA * 184320);
        __half2* opB = (__half2*)(obase + (size_t)bB * 184320);
        opA[0] = __floats2half2_rn(rA[0], rA[1]);
        opA[1] = __floats2half2_rn(rA[2], rA[3]);
        opB[0] = __floats2half2_rn(rB[0], rB[1]);
        opB[1] = __floats2half2_rn(rB[2], rB[3]);
    }
}

// =====================================================================
// Kernel 4: routing — 3 fused passes; u_hat (fp16) read ONCE per iteration.
// 512 threads = 32 groups (i-strips) x 16 lanes (k).
// =====================================================================
__device__ __forceinline__ void reduce_squash(
    const float acc[10], int tid, int g, int k,
    float red[32][160], float* sbuf, float* coef, float* vdst, float scale)
{
#pragma unroll
    for (int j = 0; j < 10; j++) red[g][j * 16 + k] = acc[j];
    __syncthreads();
    if (tid < 160) {
        float s = 0.f;
#pragma unroll
        for (int g2 = 0; g2 < 32; g2++) s += red[g2][tid];
        sbuf[tid] = s * scale;
    }
    __syncthreads();
    if (tid < 10) {
        float sn2 = 0.f;
#pragma unroll
        for (int kk = 0; kk < 16; kk++) { const float t = sbuf[tid * 16 + kk]; sn2 += t * t; }
        coef[tid] = sn2 / ((1.f + sn2) * (sqrtf(sn2) + EPSF));
    }
    __syncthreads();
    if (tid < 160) vdst[tid] = coef[tid >> 4] * sbuf[tid];
    __syncthreads();
}

__global__ __launch_bounds__(512, 2) void routing_kernel(
    const float* __restrict__ y, float* __restrict__ vout)
{
    __shared__ float red[32][160];
    __shared__ float sbuf[160];
    __shared__ float coef[10];
    __shared__ float v0[160];
    __shared__ float vcur[160];

    const int b = blockIdx.x;
    const int tid = threadIdx.x;
    const int g = tid >> 4, k = tid & 15;
    const __half* uh = g_uhath + (size_t)b * 184320;

    float acc[10];

#pragma unroll
    for (int j = 0; j < 10; j++) acc[j] = 0.f;
    for (int i = g; i < 1152; i += 32) {
        const __half* r = uh + (size_t)i * 160 + k;
#pragma unroll
        for (int j = 0; j < 10; j++) acc[j] += __half2float(r[j * 16]);
    }
    reduce_squash(acc, tid, g, k, red, sbuf, coef, v0, 0.1f);
    if (tid < 160) vcur[tid] = v0[tid];
    __syncthreads();

    for (int pass = 0; pass < 2; pass++) {
        float vr[10];
#pragma unroll
        for (int j = 0; j < 10; j++) vr[j] = vcur[j * 16 + k];
#pragma unroll
        for (int j = 0; j < 10; j++) acc[j] = 0.f;

        for (int i = g; i < 1152; i += 32) {
            const __half* r = uh + (size_t)i * 160 + k;
            float u[10], a[10];
#pragma unroll
            for (int j = 0; j < 10; j++) u[j] = __half2float(r[j * 16]);
#pragma unroll
            for (int j = 0; j < 10; j++) {
                float d = u[j] * vr[j];
                d += __shfl_xor_sync(0xffffffffu, d, 1);
                d += __shfl_xor_sync(0xffffffffu, d, 2);
                d += __shfl_xor_sync(0xffffffffu, d, 4);
                d += __shfl_xor_sync(0xffffffffu, d, 8);
                a[j] = d;
            }
            float mx = a[0];
#pragma unroll
            for (int j = 1; j < 10; j++) mx = fmaxf(mx, a[j]);
            float sum = 0.f;
#pragma unroll
            for (int j = 0; j < 10; j++) { a[j] = __expf(a[j] - mx); sum += a[j]; }
            const float inv = __fdividef(1.f, sum);
#pragma unroll
            for (int j = 0; j < 10; j++) acc[j] += a[j] * inv * u[j];
        }
        reduce_squash(acc, tid, g, k, red, sbuf, coef, vcur, 1.f);
        if (pass == 0) {
            if (tid < 160) vcur[tid] += v0[tid];
            __syncthreads();
        }
    }

    if (tid < 160) {
        const float v = vcur[tid];
        vout[(size_t)b * 160 + tid] = v;
        g_h0[(size_t)b * 160 + tid] = y[b * 10 + (tid >> 4)] * v;
    }
}

// =====================================================================
// Kernel 5-7: decoder GEMMs — BM=32, BN=64
// =====================================================================
template <int K, int N, int ACT>
__device__ __forceinline__ void gemm_body(
    const float* __restrict__ A, const float* __restrict__ W,
    const float* __restrict__ bias, float* __restrict__ C)
{
    __shared__ float As[16][36];
    __shared__ float Bs[16][68];
    const int tid = threadIdx.x;
    const int n0 = blockIdx.x * 64;
    const int m0 = blockIdx.y * 32;
    const int ty = tid >> 4, tx = tid & 15;
    const int ar = tid >> 3, ak = (tid & 7) * 2;
    const int bk = tid >> 4, bc = (tid & 15) * 4;

    float acc[2][4];
#pragma unroll
    for (int r = 0; r < 2; r++)
#pragma unroll
        for (int q = 0; q < 4; q++) acc[r][q] = 0.f;

    for (int k0 = 0; k0 < K; k0 += 16) {
        const float2 av = *(const float2*)(A + (size_t)(m0 + ar) * K + k0 + ak);
        float4 bv = make_float4(0.f, 0.f, 0.f, 0.f);
        if (n0 + bc < N) bv = *(const float4*)(W + (size_t)(k0 + bk) * N + n0 + bc);
        __syncthreads();
        As[ak][ar] = av.x;
        As[ak + 1][ar] = av.y;
        *(float4*)&Bs[bk][bc] = bv;
        __syncthreads();
#pragma unroll
        for (int kk = 0; kk < 16; kk++) {
            const float a0 = As[kk][ty * 2];
            const float a1 = As[kk][ty * 2 + 1];
            const float4 b4 = *(const float4*)&Bs[kk][tx * 4];
            const float bb[4] = {b4.x, b4.y, b4.z, b4.w};
#pragma unroll
            for (int q = 0; q < 4; q++) {
                acc[0][q] += a0 * bb[q];
                acc[1][q] += a1 * bb[q];
            }
        }
    }

    if (n0 + tx * 4 < N) {
        const float4 bv = *(const float4*)(bias + n0 + tx * 4);
        const float bb[4] = {bv.x, bv.y, bv.z, bv.w};
#pragma unroll
        for (int r = 0; r < 2; r++) {
            const int mm = m0 + ty * 2 + r;
            float o[4];
#pragma unroll
            for (int q = 0; q < 4; q++) {
                float v = acc[r][q] + bb[q];
                if (ACT == 0) v = fmaxf(v, 0.f);
                else          v = 1.f / (1.f + __expf(-v));
                o[q] = v;
            }
            *(float4*)(C + (size_t)mm * N + n0 + tx * 4) = make_float4(o[0], o[1], o[2], o[3]);
        }
    }
}

__global__ __launch_bounds__(256) void dec1_kernel(const float* __restrict__ W,
                                                   const float* __restrict__ b)
{ gemm_body<160, 512, 0>(g_h0, W, b, g_h1); }

__global__ __launch_bounds__(256) void dec2_kernel(const float* __restrict__ W,
                                                   const float* __restrict__ b)
{ gemm_body<512, 1024, 0>(g_h1, W, b, g_h2); }

__global__ __launch_bounds__(256) void dec3_kernel(const float* __restrict__ W,
                                                   const float* __restrict__ b,
                                                   float* __restrict__ out)
{ gemm_body<1024, 784, 1>(g_h2, W, b, out); }

// =====================================================================
extern "C" void kernel_launch(void* const* d_in, const int* in_sizes, int n_in,
                              void* d_out, int out_size)
{
    const float* input_x = (const float*)d_in[0];
    const float* y       = (const float*)d_in[1];
    const float* conv1_w = (const float*)d_in[2];
    const float* conv1_b = (const float*)d_in[3];
    const float* pc_w    = (const float*)d_in[4];
    const float* pc_b    = (const float*)d_in[5];
    const float* w_pose  = (const float*)d_in[6];
    const float* d1_w    = (const float*)d_in[7];
    const float* d1_b    = (const float*)d_in[8];
    const float* d2_w    = (const float*)d_in[9];
    const float* d2_b    = (const float*)d_in[10];
    const float* d3_w    = (const float*)d_in[11];
    const float* d3_b    = (const float*)d_in[12];
    float* out = (float*)d_out;

    cudaFuncSetAttribute(pc_kernel, cudaFuncAttributeMaxDynamicSharedMemorySize,
                         PC_NSTAGE * PC_STAGE);

    init_kernel<<<1, 1>>>();
    conv1_maxB_kernel<<<640, 256>>>(input_x, conv1_w, conv1_b, pc_w);
    quant_kernel<<<30784, 256>>>(pc_w);
    pc_kernel<<<dim3(72, 2), 256, PC_NSTAGE * PC_STAGE>>>(pc_b);
    uhat_kernel<<<1152, 320>>>(w_pose);
    routing_kernel<<<BATCH, 512>>>(y, out);
    dec1_kernel<<<dim3(8, 8), 256>>>(d1_w, d1_b);
    dec2_kernel<<<dim3(16, 8), 256>>>(d2_w, d2_b);
    dec3_kernel<<<dim3(13, 8), 256>>>(d3_w, d3_b, out + BATCH * 160);
    (void)in_sizes; (void)n_in; (void)out_size;
}